// round 4
// baseline (speedup 1.0000x reference)
#include <cuda_runtime.h>
#include <cuda_bf16.h>
#include <cstdint>
#include <math.h>

// Problem constants
#define B_   16
#define Q_   300
#define S_   8400
#define DM   256
#define NH   8
#define HD   32
#define LP_  12
#define BQ   (B_*Q_)          // 4800
#define MVAL (B_*S_)          // 134400

// Scratch (static device globals — no allocation)
__device__ float g_value[(size_t)MVAL * DM];   // [B,S,256]
__device__ float g_oa[(size_t)BQ * 288];       // fused offsets(192)+attn logits(96)
__device__ float g_msda[(size_t)BQ * DM];

// ===========================================================================
// tf32 helpers
// ===========================================================================
__device__ __forceinline__ uint32_t f2tf32(float f) {
    uint32_t u;
    asm("cvt.rna.tf32.f32 %0, %1;" : "=r"(u) : "f"(f));
    return u;
}

__device__ __forceinline__ void mma_m16n8k8_tf32(
    float c[4], const uint32_t a[4], const uint32_t b[2])
{
    asm volatile(
        "mma.sync.aligned.m16n8k8.row.col.f32.tf32.tf32.f32 "
        "{%0,%1,%2,%3}, {%4,%5,%6,%7}, {%8,%9}, {%0,%1,%2,%3};"
        : "+f"(c[0]), "+f"(c[1]), "+f"(c[2]), "+f"(c[3])
        : "r"(a[0]), "r"(a[1]), "r"(a[2]), "r"(a[3]),
          "r"(b[0]), "r"(b[1]));
}

// ===========================================================================
// tf32 tensor-core GEMM: C[M,256] = A[M,256] @ W[256,256]^T + bias
// CTA tile 128x128, 8 warps (4m x 2n), warp tile 32x64, BK=32, double-buffer.
// SMEM layout: PADW=40 words/row; k-interleaved within each group of 8:
//   word position p of group g holds k = g*8 + 4*(p&1) + (p>>1)
// => fragment pair (k+tig, k+tig+4) is contiguous -> LDS64, conflict-free.
// ===========================================================================
#define GK    256
#define GBK   32
#define GNC   (GK / GBK)       // 8 chunks
#define PADW  40
#define TILEW (128 * PADW)     // 5120 words
#define BUFW  (2 * TILEW)      // A + B per buffer

__global__ __launch_bounds__(256) void gemm_tf32_nt(
    const float* __restrict__ A, const float* __restrict__ W,
    const float* __restrict__ bias, float* __restrict__ C, int M)
{
    extern __shared__ uint32_t sm[];

    const int tid  = threadIdx.x;
    const int wid  = tid >> 5;
    const int lane = tid & 31;
    const int grp  = lane >> 2;        // 0..7
    const int tig  = lane & 3;         // 0..3

    const int wm = (wid & 3) * 32;
    const int wn = (wid >> 2) * 64;
    const int bm = blockIdx.y * 128;
    const int bn = blockIdx.x * 128;

    float acc[2][8][4];
#pragma unroll
    for (int i = 0; i < 2; i++)
#pragma unroll
        for (int j = 0; j < 8; j++)
#pragma unroll
            for (int l = 0; l < 4; l++) acc[i][j][l] = 0.f;

    // load mapping: 8 threads per row; thread j: group g=j>>1, half h=j&1
    const int lrow = tid >> 3;         // 0..31
    const int lj   = tid & 7;
    const int lg   = lj >> 1;
    const int lh   = lj & 1;
    const int koff = lg * 8 + 2 * lh;  // first float2 k offset

    // ---- preload chunk 0 ----
    {
        uint32_t* sA = sm;
        uint32_t* sB = sm + TILEW;
#pragma unroll
        for (int t = 0; t < 4; ++t) {
            int row = lrow + t * 32;
            int mg  = bm + row;
            float2 v0 = make_float2(0.f, 0.f), v1 = v0;
            if (mg < M) {
                v0 = *(const float2*)(A + (size_t)mg * GK + koff);
                v1 = *(const float2*)(A + (size_t)mg * GK + koff + 4);
            }
            *(uint4*)&sA[row * PADW + lj * 4] =
                make_uint4(f2tf32(v0.x), f2tf32(v1.x), f2tf32(v0.y), f2tf32(v1.y));
        }
#pragma unroll
        for (int t = 0; t < 4; ++t) {
            int row = lrow + t * 32;
            float2 v0 = *(const float2*)(W + (size_t)(bn + row) * GK + koff);
            float2 v1 = *(const float2*)(W + (size_t)(bn + row) * GK + koff + 4);
            *(uint4*)&sB[row * PADW + lj * 4] =
                make_uint4(f2tf32(v0.x), f2tf32(v1.x), f2tf32(v0.y), f2tf32(v1.y));
        }
    }
    __syncthreads();

    for (int c = 0; c < GNC; ++c) {
        // ---- prefetch chunk c+1 into registers ----
        float2 pa0[4], pa1[4], pb0[4], pb1[4];
        if (c + 1 < GNC) {
            const int k0 = (c + 1) * GBK;
#pragma unroll
            for (int t = 0; t < 4; ++t) {
                int row = lrow + t * 32;
                int mg  = bm + row;
                pa0[t] = make_float2(0.f, 0.f); pa1[t] = pa0[t];
                if (mg < M) {
                    pa0[t] = *(const float2*)(A + (size_t)mg * GK + k0 + koff);
                    pa1[t] = *(const float2*)(A + (size_t)mg * GK + k0 + koff + 4);
                }
            }
#pragma unroll
            for (int t = 0; t < 4; ++t) {
                int row = lrow + t * 32;
                pb0[t] = *(const float2*)(W + (size_t)(bn + row) * GK + k0 + koff);
                pb1[t] = *(const float2*)(W + (size_t)(bn + row) * GK + k0 + koff + 4);
            }
        }

        // ---- compute chunk c ----
        {
            const uint32_t* sA = sm + (c & 1) * BUFW;
            const uint32_t* sB = sA + TILEW;
#pragma unroll
            for (int ks = 0; ks < 4; ++ks) {
                const int base = ks * 8 + 2 * tig;
                uint32_t af[2][4];
#pragma unroll
                for (int mf = 0; mf < 2; ++mf) {
                    const int m = wm + mf * 16 + grp;
                    uint2 a0 = *(const uint2*)&sA[m * PADW + base];
                    uint2 a1 = *(const uint2*)&sA[(m + 8) * PADW + base];
                    af[mf][0] = a0.x; af[mf][1] = a1.x;
                    af[mf][2] = a0.y; af[mf][3] = a1.y;
                }
                uint32_t bf[8][2];
#pragma unroll
                for (int nf = 0; nf < 8; ++nf) {
                    const int n = wn + nf * 8 + grp;
                    uint2 bb = *(const uint2*)&sB[n * PADW + base];
                    bf[nf][0] = bb.x; bf[nf][1] = bb.y;
                }
#pragma unroll
                for (int mf = 0; mf < 2; ++mf)
#pragma unroll
                    for (int nf = 0; nf < 8; ++nf)
                        mma_m16n8k8_tf32(acc[mf][nf], af[mf], bf[nf]);
            }
        }

        // ---- store prefetched chunk to other buffer ----
        if (c + 1 < GNC) {
            uint32_t* sA = sm + ((c + 1) & 1) * BUFW;
            uint32_t* sB = sA + TILEW;
#pragma unroll
            for (int t = 0; t < 4; ++t) {
                int row = lrow + t * 32;
                *(uint4*)&sA[row * PADW + lj * 4] =
                    make_uint4(f2tf32(pa0[t].x), f2tf32(pa1[t].x),
                               f2tf32(pa0[t].y), f2tf32(pa1[t].y));
            }
#pragma unroll
            for (int t = 0; t < 4; ++t) {
                int row = lrow + t * 32;
                *(uint4*)&sB[row * PADW + lj * 4] =
                    make_uint4(f2tf32(pb0[t].x), f2tf32(pb1[t].x),
                               f2tf32(pb0[t].y), f2tf32(pb1[t].y));
            }
            __syncthreads();
        }
    }

    // ---- epilogue ----
#pragma unroll
    for (int mf = 0; mf < 2; ++mf) {
        const int mlo = bm + wm + mf * 16 + grp;
#pragma unroll
        for (int nf = 0; nf < 8; ++nf) {
            const int col = bn + wn + nf * 8 + 2 * tig;
            const float bx = __ldg(&bias[col]);
            const float by = __ldg(&bias[col + 1]);
            if (mlo < M) {
                float2 v = make_float2(acc[mf][nf][0] + bx, acc[mf][nf][1] + by);
                *(float2*)(C + (size_t)mlo * DM + col) = v;
            }
            if (mlo + 8 < M) {
                float2 v = make_float2(acc[mf][nf][2] + bx, acc[mf][nf][3] + by);
                *(float2*)(C + (size_t)(mlo + 8) * DM + col) = v;
            }
        }
    }
}

// ---------------------------------------------------------------------------
// Fused offsets+attn projection: C[M,288], rows 0..191 from Woff, 192..287 Wattn
// ---------------------------------------------------------------------------
#define BM 128
#define BN 64
#define BK 16
#define TM 8
#define TN 4

__global__ __launch_bounds__(256) void gemm_dual(
    const float* __restrict__ A,
    const float* __restrict__ Woff, const float* __restrict__ boff,
    const float* __restrict__ Wattn, const float* __restrict__ battn,
    float* __restrict__ C, int M, int N, int K)
{
    __shared__ float As[BK][BM + 4];
    __shared__ float Bs[BK][BN];

    const int tx = threadIdx.x & 15;
    const int ty = threadIdx.x >> 4;
    const int bm = blockIdx.y * BM;
    const int bn = blockIdx.x * BN;

    float acc[TM][TN];
#pragma unroll
    for (int i = 0; i < TM; i++)
#pragma unroll
        for (int j = 0; j < TN; j++) acc[i][j] = 0.f;

    for (int k0 = 0; k0 < K; k0 += BK) {
#pragma unroll
        for (int t = 0; t < (BM * BK) / 256; ++t) {
            int i = threadIdx.x + t * 256;
            int m = i / BK, k = i % BK;
            float v = 0.f;
            if (bm + m < M) v = A[(size_t)(bm + m) * K + k0 + k];
            As[k][m] = v;
        }
#pragma unroll
        for (int t = 0; t < (BN * BK) / 256; ++t) {
            int i = threadIdx.x + t * 256;
            int n = i / BK, k = i % BK;
            int ng = bn + n;
            float v = 0.f;
            if (ng < N) {
                const float* wr = (ng < 192) ? (Woff + (size_t)ng * K)
                                             : (Wattn + (size_t)(ng - 192) * K);
                v = wr[k0 + k];
            }
            Bs[k][n] = v;
        }
        __syncthreads();

#pragma unroll
        for (int k = 0; k < BK; ++k) {
            float a[TM], b[TN];
#pragma unroll
            for (int i = 0; i < TM; i++) a[i] = As[k][ty * TM + i];
#pragma unroll
            for (int j = 0; j < TN; j++) b[j] = Bs[k][tx * TN + j];
#pragma unroll
            for (int i = 0; i < TM; i++)
#pragma unroll
                for (int j = 0; j < TN; j++) acc[i][j] += a[i] * b[j];
        }
        __syncthreads();
    }

#pragma unroll
    for (int i = 0; i < TM; i++) {
        int m = bm + ty * TM + i;
        if (m >= M) continue;
#pragma unroll
        for (int j = 0; j < TN; j++) {
            int n = bn + tx * TN + j;
            if (n < N) {
                float bia = (n < 192) ? boff[n] : battn[n - 192];
                C[(size_t)m * N + n] = acc[i][j] + bia;
            }
        }
    }
}

// ---------------------------------------------------------------------------
// Sampling kernel v2: block per (b,q).
// Phase A: threads 0..95 precompute per-(head,point) offsets+weights in SMEM.
// Phase B: warp = head, lane = channel: 12 x (4 gathers + 4 FMA).
// ---------------------------------------------------------------------------
__global__ __launch_bounds__(256) void msda_sample2(
    const float* __restrict__ value,
    const float* __restrict__ oa,      // [BQ, 288]: 0..191 offs, 192..287 logits
    const float* __restrict__ refp,
    float* __restrict__ out)
{
    __shared__ float  s_logit[96];
    __shared__ float2 s_mxinv[8];
    __shared__ int4   s_ofs[96];
    __shared__ float4 s_wts[96];

    const int bq = blockIdx.x;
    const int b  = bq / Q_;
    const int t  = threadIdx.x;

    if (t < 96) s_logit[t] = oa[(size_t)bq * 288 + 192 + t];
    __syncthreads();

    if (t < 8) {
        float mx = -1e30f;
#pragma unroll
        for (int p = 0; p < LP_; p++) mx = fmaxf(mx, s_logit[t * LP_ + p]);
        float s = 0.f;
#pragma unroll
        for (int p = 0; p < LP_; p++) s += __expf(s_logit[t * LP_ + p] - mx);
        s_mxinv[t] = make_float2(mx, 1.f / s);
    }
    __syncthreads();

    if (t < 96) {
        const int h = t / LP_;
        const int p = t - h * LP_;
        const float2 mi = s_mxinv[h];
        const float aw = __expf(s_logit[t] - mi.x) * mi.y;

        const float rx = refp[bq * 4 + 0];
        const float ry = refp[bq * 4 + 1];
        const float rw = refp[bq * 4 + 2];
        const float rh = refp[bq * 4 + 3];

        const float ox = oa[(size_t)bq * 288 + h * 24 + 2 * p + 0];
        const float oy = oa[(size_t)bq * 288 + h * 24 + 2 * p + 1];

        const int lvl   = p >> 2;
        const int Wl    = (lvl == 0) ? 80 : (lvl == 1) ? 40 : 20;
        const int start = (lvl == 0) ? 0 : (lvl == 1) ? 6400 : 8000;

        const float gx = (rx + ox * 0.125f * rw) * (float)Wl - 0.5f;
        const float gy = (ry + oy * 0.125f * rh) * (float)Wl - 0.5f;

        const float x0f = floorf(gx), y0f = floorf(gy);
        const int x0 = (int)x0f, y0 = (int)y0f;
        const int x1 = x0 + 1,  y1 = y0 + 1;
        const float wx1 = gx - x0f, wx0 = 1.f - wx1;
        const float wy1 = gy - y0f, wy0 = 1.f - wy1;

        const bool xv0 = (x0 >= 0) & (x0 < Wl);
        const bool xv1 = (x1 >= 0) & (x1 < Wl);
        const bool yv0 = (y0 >= 0) & (y0 < Wl);
        const bool yv1 = (y1 >= 0) & (y1 < Wl);

        const int x0c = min(max(x0, 0), Wl - 1);
        const int x1c = min(max(x1, 0), Wl - 1);
        const int y0c = min(max(y0, 0), Wl - 1);
        const int y1c = min(max(y1, 0), Wl - 1);

        const int rb = b * S_ + start;
        const int r0 = rb + y0c * Wl;
        const int r1 = rb + y1c * Wl;
        const int hb = h * HD;

        int4 o;
        o.x = (r0 + x0c) * DM + hb;
        o.y = (r0 + x1c) * DM + hb;
        o.z = (r1 + x0c) * DM + hb;
        o.w = (r1 + x1c) * DM + hb;

        float4 w;
        w.x = aw * wx0 * wy0 * (float)(xv0 & yv0);
        w.y = aw * wx1 * wy0 * (float)(xv1 & yv0);
        w.z = aw * wx0 * wy1 * (float)(xv0 & yv1);
        w.w = aw * wx1 * wy1 * (float)(xv1 & yv1);

        s_ofs[t] = o;
        s_wts[t] = w;
    }
    __syncthreads();

    const int h    = t >> 5;
    const int lane = t & 31;
    float acc = 0.f;
#pragma unroll
    for (int p = 0; p < LP_; p++) {
        const int4   o = s_ofs[h * LP_ + p];
        const float4 w = s_wts[h * LP_ + p];
        acc += w.x * __ldg(&value[o.x + lane]);
        acc += w.y * __ldg(&value[o.y + lane]);
        acc += w.z * __ldg(&value[o.z + lane]);
        acc += w.w * __ldg(&value[o.w + lane]);
    }
    out[(size_t)bq * DM + h * HD + lane] = acc;
}

// ---------------------------------------------------------------------------
extern "C" void kernel_launch(void* const* d_in, const int* in_sizes, int n_in,
                              void* d_out, int out_size)
{
    const float* hs      = (const float*)d_in[0];
    const float* ehs     = (const float*)d_in[1];
    const float* refp    = (const float*)d_in[2];
    const float* w_value = (const float*)d_in[3];
    const float* b_value = (const float*)d_in[4];
    const float* w_off   = (const float*)d_in[5];
    const float* b_off   = (const float*)d_in[6];
    const float* w_attn  = (const float*)d_in[7];
    const float* b_attn  = (const float*)d_in[8];
    const float* w_out   = (const float*)d_in[9];
    const float* b_out   = (const float*)d_in[10];
    float* out = (float*)d_out;

    float *pval, *poa, *pmsda;
    cudaGetSymbolAddress((void**)&pval,  g_value);
    cudaGetSymbolAddress((void**)&poa,   g_oa);
    cudaGetSymbolAddress((void**)&pmsda, g_msda);

    const int dyn_smem = 2 * BUFW * 4;   // 81920 bytes
    cudaFuncSetAttribute(gemm_tf32_nt,
                         cudaFuncAttributeMaxDynamicSharedMemorySize, dyn_smem);

    // 1. value = ehs @ w_value^T + b_value   (tf32 tensor cores)
    gemm_tf32_nt<<<dim3(2, MVAL / 128), 256, dyn_smem>>>(ehs, w_value, b_value,
                                                         pval, MVAL);
    // 2. fused offsets+attn projections (N=288)
    gemm_dual<<<dim3(5, (BQ + BM - 1) / BM), 256>>>(hs, w_off, b_off,
                                                    w_attn, b_attn, poa,
                                                    BQ, 288, DM);
    // 3. softmax + bilinear sampling + weighted sum
    msda_sample2<<<BQ, 256>>>(pval, poa, refp, pmsda);
    // 4. out = msda @ w_out^T + b_out   (tf32 tensor cores)
    gemm_tf32_nt<<<dim3(2, (BQ + 127) / 128), 256, dyn_smem>>>(pmsda, w_out,
                                                               b_out, out, BQ);
}

// round 5
// speedup vs baseline: 1.0288x; 1.0288x over previous
#include <cuda_runtime.h>
#include <cuda_bf16.h>
#include <cstdint>
#include <math.h>

// Problem constants
#define B_   16
#define Q_   300
#define S_   8400
#define DM   256
#define NH   8
#define HD   32
#define LP_  12
#define BQ   (B_*Q_)          // 4800
#define MVAL (B_*S_)          // 134400

// Scratch (static device globals — no allocation)
__device__ float g_value[(size_t)MVAL * DM];   // [B,S,256]
__device__ float g_oa[(size_t)BQ * 288];       // fused offsets(192)+attn logits(96)
__device__ float g_msda[(size_t)BQ * DM];

// ===========================================================================
// helpers
// ===========================================================================
__device__ __forceinline__ uint32_t f2tf32(float f) {
    uint32_t u;
    asm("cvt.rna.tf32.f32 %0, %1;" : "=r"(u) : "f"(f));
    return u;
}
__device__ __forceinline__ void mma_m16n8k8_tf32(
    float c[4], const uint32_t a[4], const uint32_t b[2])
{
    asm volatile(
        "mma.sync.aligned.m16n8k8.row.col.f32.tf32.tf32.f32 "
        "{%0,%1,%2,%3}, {%4,%5,%6,%7}, {%8,%9}, {%0,%1,%2,%3};"
        : "+f"(c[0]), "+f"(c[1]), "+f"(c[2]), "+f"(c[3])
        : "r"(a[0]), "r"(a[1]), "r"(a[2]), "r"(a[3]),
          "r"(b[0]), "r"(b[1]));
}
__device__ __forceinline__ void cp_async16(uint32_t dst, const void* src, bool valid) {
    int sz = valid ? 16 : 0;
    asm volatile("cp.async.cg.shared.global [%0], [%1], 16, %2;"
                 :: "r"(dst), "l"(src), "r"(sz));
}
#define CP_COMMIT()  asm volatile("cp.async.commit_group;" ::: "memory")
#define CP_WAIT(N)   asm volatile("cp.async.wait_group %0;" :: "n"(N) : "memory")

// ===========================================================================
// tf32 GEMM: C[M,256] = A[M,256] @ W[256,256]^T + bias
// CTA tile 128x256 (full N), 8 warps (4m x 2n), warp tile 32x128.
// BK=16, 4-stage cp.async pipeline. SMEM rows padded to 20 words (80B):
// 16B-aligned for cp.async, conflict-free for scalar fragment LDS.
// fp32 stored raw; cvt.rna.tf32 applied at fragment load.
// ===========================================================================
#define GK      256
#define GBK     16
#define NCH     (GK / GBK)      // 16 chunks
#define PADB    20              // words per row
#define AROWS   128
#define BROWS   256
#define AW      (AROWS * PADB)  // 2560 words
#define BW      (BROWS * PADB)  // 5120 words
#define STAGEW  (AW + BW)       // 7680 words = 30720 B
#define NSTAGE  4

__global__ __launch_bounds__(256, 1) void gemm_tf32_nt(
    const float* __restrict__ A, const float* __restrict__ W,
    const float* __restrict__ bias, float* __restrict__ C, int M)
{
    extern __shared__ float sm[];

    const int tid  = threadIdx.x;
    const int wid  = tid >> 5;
    const int lane = tid & 31;
    const int grp  = lane >> 2;        // 0..7
    const int tig  = lane & 3;         // 0..3

    const int wm = (wid & 3) * 32;     // warp m offset
    const int wn = (wid >> 2) * 128;   // warp n offset
    const int m0 = blockIdx.x * 128;

    const uint32_t smem_u32 = (uint32_t)__cvta_generic_to_shared(sm);

    float acc[2][16][4];
#pragma unroll
    for (int i = 0; i < 2; i++)
#pragma unroll
        for (int j = 0; j < 16; j++)
#pragma unroll
            for (int l = 0; l < 4; l++) acc[i][j][l] = 0.f;

    // cp.async issue for chunk c into stage s
    auto issue = [&](int c, int s) {
        const uint32_t abase = smem_u32 + (uint32_t)(s * STAGEW) * 4u;
        const uint32_t bbase = abase + (uint32_t)AW * 4u;
        const int k0 = c * GBK;
        // A: 128 rows x 4 16B-chunks = 512, 2 per thread
#pragma unroll
        for (int it = 0; it < 2; ++it) {
            int idx = tid + it * 256;
            int row = idx >> 2, col = idx & 3;
            bool v = (m0 + row) < M;
            const float* src = A + (size_t)(m0 + row) * GK + k0 + col * 4;
            cp_async16(abase + (uint32_t)(row * PADB + col * 4) * 4u, src, v);
        }
        // B: 256 rows x 4 = 1024, 4 per thread
#pragma unroll
        for (int it = 0; it < 4; ++it) {
            int idx = tid + it * 256;
            int row = idx >> 2, col = idx & 3;
            const float* src = W + (size_t)row * GK + k0 + col * 4;
            cp_async16(bbase + (uint32_t)(row * PADB + col * 4) * 4u, src, true);
        }
        CP_COMMIT();
    };

    // prologue: stages 0..2
    issue(0, 0);
    issue(1, 1);
    issue(2, 2);

    for (int c = 0; c < NCH; ++c) {
        CP_WAIT(2);           // oldest outstanding group (chunk c) complete
        __syncthreads();      // all warps see stage, and prior compute done

        if (c + 3 < NCH) issue(c + 3, (c + 3) & 3);
        else CP_COMMIT();     // keep group count aligned

        const float* sA = sm + (c & 3) * STAGEW;
        const float* sB = sA + AW;

#pragma unroll
        for (int ks = 0; ks < 2; ++ks) {
            const int k = ks * 8;
            uint32_t af[2][4];
#pragma unroll
            for (int mf = 0; mf < 2; ++mf) {
                const int m = wm + mf * 16 + grp;
                af[mf][0] = f2tf32(sA[m * PADB + k + tig]);
                af[mf][1] = f2tf32(sA[(m + 8) * PADB + k + tig]);
                af[mf][2] = f2tf32(sA[m * PADB + k + tig + 4]);
                af[mf][3] = f2tf32(sA[(m + 8) * PADB + k + tig + 4]);
            }
#pragma unroll
            for (int nf = 0; nf < 16; ++nf) {
                const int n = wn + nf * 8 + grp;
                uint32_t bf[2];
                bf[0] = f2tf32(sB[n * PADB + k + tig]);
                bf[1] = f2tf32(sB[n * PADB + k + tig + 4]);
#pragma unroll
                for (int mf = 0; mf < 2; ++mf)
                    mma_m16n8k8_tf32(acc[mf][nf], af[mf], bf);
            }
        }
        __syncthreads();      // compute done before stage reuse next iter
    }

    // ---- epilogue ----
#pragma unroll
    for (int mf = 0; mf < 2; ++mf) {
        const int mlo = m0 + wm + mf * 16 + grp;
#pragma unroll
        for (int nf = 0; nf < 16; ++nf) {
            const int col = wn + nf * 8 + 2 * tig;
            const float bx = __ldg(&bias[col]);
            const float by = __ldg(&bias[col + 1]);
            if (mlo < M) {
                float2 v = make_float2(acc[mf][nf][0] + bx, acc[mf][nf][1] + by);
                *(float2*)(C + (size_t)mlo * DM + col) = v;
            }
            if (mlo + 8 < M) {
                float2 v = make_float2(acc[mf][nf][2] + bx, acc[mf][nf][3] + by);
                *(float2*)(C + (size_t)(mlo + 8) * DM + col) = v;
            }
        }
    }
}

// ---------------------------------------------------------------------------
// Fused offsets+attn projection: C[M,288], rows 0..191 Woff, 192..287 Wattn
// ---------------------------------------------------------------------------
#define BM 128
#define BN 64
#define BK 16
#define TM 8
#define TN 4

__global__ __launch_bounds__(256) void gemm_dual(
    const float* __restrict__ A,
    const float* __restrict__ Woff, const float* __restrict__ boff,
    const float* __restrict__ Wattn, const float* __restrict__ battn,
    float* __restrict__ C, int M, int N, int K)
{
    __shared__ float As[BK][BM + 4];
    __shared__ float Bs[BK][BN];

    const int tx = threadIdx.x & 15;
    const int ty = threadIdx.x >> 4;
    const int bm = blockIdx.y * BM;
    const int bn = blockIdx.x * BN;

    float acc[TM][TN];
#pragma unroll
    for (int i = 0; i < TM; i++)
#pragma unroll
        for (int j = 0; j < TN; j++) acc[i][j] = 0.f;

    for (int k0 = 0; k0 < K; k0 += BK) {
#pragma unroll
        for (int t = 0; t < (BM * BK) / 256; ++t) {
            int i = threadIdx.x + t * 256;
            int m = i / BK, k = i % BK;
            float v = 0.f;
            if (bm + m < M) v = A[(size_t)(bm + m) * K + k0 + k];
            As[k][m] = v;
        }
#pragma unroll
        for (int t = 0; t < (BN * BK) / 256; ++t) {
            int i = threadIdx.x + t * 256;
            int n = i / BK, k = i % BK;
            int ng = bn + n;
            float v = 0.f;
            if (ng < N) {
                const float* wr = (ng < 192) ? (Woff + (size_t)ng * K)
                                             : (Wattn + (size_t)(ng - 192) * K);
                v = wr[k0 + k];
            }
            Bs[k][n] = v;
        }
        __syncthreads();

#pragma unroll
        for (int k = 0; k < BK; ++k) {
            float a[TM], b[TN];
#pragma unroll
            for (int i = 0; i < TM; i++) a[i] = As[k][ty * TM + i];
#pragma unroll
            for (int j = 0; j < TN; j++) b[j] = Bs[k][tx * TN + j];
#pragma unroll
            for (int i = 0; i < TM; i++)
#pragma unroll
                for (int j = 0; j < TN; j++) acc[i][j] += a[i] * b[j];
        }
        __syncthreads();
    }

#pragma unroll
    for (int i = 0; i < TM; i++) {
        int m = bm + ty * TM + i;
        if (m >= M) continue;
#pragma unroll
        for (int j = 0; j < TN; j++) {
            int n = bn + tx * TN + j;
            if (n < N) {
                float bia = (n < 192) ? boff[n] : battn[n - 192];
                C[(size_t)m * N + n] = acc[i][j] + bia;
            }
        }
    }
}

// ---------------------------------------------------------------------------
// Sampling kernel: block per (b,q).
// Phase A: threads 0..95 precompute per-(head,point) offsets+weights in SMEM.
// Phase B: warp = head, lane = channel: 12 x (4 gathers + 4 FMA).
// ---------------------------------------------------------------------------
__global__ __launch_bounds__(256) void msda_sample2(
    const float* __restrict__ value,
    const float* __restrict__ oa,
    const float* __restrict__ refp,
    float* __restrict__ out)
{
    __shared__ float  s_logit[96];
    __shared__ float2 s_mxinv[8];
    __shared__ int4   s_ofs[96];
    __shared__ float4 s_wts[96];

    const int bq = blockIdx.x;
    const int b  = bq / Q_;
    const int t  = threadIdx.x;

    if (t < 96) s_logit[t] = oa[(size_t)bq * 288 + 192 + t];
    __syncthreads();

    if (t < 8) {
        float mx = -1e30f;
#pragma unroll
        for (int p = 0; p < LP_; p++) mx = fmaxf(mx, s_logit[t * LP_ + p]);
        float s = 0.f;
#pragma unroll
        for (int p = 0; p < LP_; p++) s += __expf(s_logit[t * LP_ + p] - mx);
        s_mxinv[t] = make_float2(mx, 1.f / s);
    }
    __syncthreads();

    if (t < 96) {
        const int h = t / LP_;
        const int p = t - h * LP_;
        const float2 mi = s_mxinv[h];
        const float aw = __expf(s_logit[t] - mi.x) * mi.y;

        const float rx = refp[bq * 4 + 0];
        const float ry = refp[bq * 4 + 1];
        const float rw = refp[bq * 4 + 2];
        const float rh = refp[bq * 4 + 3];

        const float ox = oa[(size_t)bq * 288 + h * 24 + 2 * p + 0];
        const float oy = oa[(size_t)bq * 288 + h * 24 + 2 * p + 1];

        const int lvl   = p >> 2;
        const int Wl    = (lvl == 0) ? 80 : (lvl == 1) ? 40 : 20;
        const int start = (lvl == 0) ? 0 : (lvl == 1) ? 6400 : 8000;

        const float gx = (rx + ox * 0.125f * rw) * (float)Wl - 0.5f;
        const float gy = (ry + oy * 0.125f * rh) * (float)Wl - 0.5f;

        const float x0f = floorf(gx), y0f = floorf(gy);
        const int x0 = (int)x0f, y0 = (int)y0f;
        const int x1 = x0 + 1,  y1 = y0 + 1;
        const float wx1 = gx - x0f, wx0 = 1.f - wx1;
        const float wy1 = gy - y0f, wy0 = 1.f - wy1;

        const bool xv0 = (x0 >= 0) & (x0 < Wl);
        const bool xv1 = (x1 >= 0) & (x1 < Wl);
        const bool yv0 = (y0 >= 0) & (y0 < Wl);
        const bool yv1 = (y1 >= 0) & (y1 < Wl);

        const int x0c = min(max(x0, 0), Wl - 1);
        const int x1c = min(max(x1, 0), Wl - 1);
        const int y0c = min(max(y0, 0), Wl - 1);
        const int y1c = min(max(y1, 0), Wl - 1);

        const int rb = b * S_ + start;
        const int r0 = rb + y0c * Wl;
        const int r1 = rb + y1c * Wl;
        const int hb = h * HD;

        int4 o;
        o.x = (r0 + x0c) * DM + hb;
        o.y = (r0 + x1c) * DM + hb;
        o.z = (r1 + x0c) * DM + hb;
        o.w = (r1 + x1c) * DM + hb;

        float4 w;
        w.x = aw * wx0 * wy0 * (float)(xv0 & yv0);
        w.y = aw * wx1 * wy0 * (float)(xv1 & yv0);
        w.z = aw * wx0 * wy1 * (float)(xv0 & yv1);
        w.w = aw * wx1 * wy1 * (float)(xv1 & yv1);

        s_ofs[t] = o;
        s_wts[t] = w;
    }
    __syncthreads();

    const int h    = t >> 5;
    const int lane = t & 31;
    float acc = 0.f;
#pragma unroll
    for (int p = 0; p < LP_; p++) {
        const int4   o = s_ofs[h * LP_ + p];
        const float4 w = s_wts[h * LP_ + p];
        acc += w.x * __ldg(&value[o.x + lane]);
        acc += w.y * __ldg(&value[o.y + lane]);
        acc += w.z * __ldg(&value[o.z + lane]);
        acc += w.w * __ldg(&value[o.w + lane]);
    }
    out[(size_t)bq * DM + h * HD + lane] = acc;
}

// ---------------------------------------------------------------------------
extern "C" void kernel_launch(void* const* d_in, const int* in_sizes, int n_in,
                              void* d_out, int out_size)
{
    const float* hs      = (const float*)d_in[0];
    const float* ehs     = (const float*)d_in[1];
    const float* refp    = (const float*)d_in[2];
    const float* w_value = (const float*)d_in[3];
    const float* b_value = (const float*)d_in[4];
    const float* w_off   = (const float*)d_in[5];
    const float* b_off   = (const float*)d_in[6];
    const float* w_attn  = (const float*)d_in[7];
    const float* b_attn  = (const float*)d_in[8];
    const float* w_out   = (const float*)d_in[9];
    const float* b_out   = (const float*)d_in[10];
    float* out = (float*)d_out;

    float *pval, *poa, *pmsda;
    cudaGetSymbolAddress((void**)&pval,  g_value);
    cudaGetSymbolAddress((void**)&poa,   g_oa);
    cudaGetSymbolAddress((void**)&pmsda, g_msda);

    const int dyn_smem = NSTAGE * STAGEW * 4;   // 122880 bytes
    cudaFuncSetAttribute(gemm_tf32_nt,
                         cudaFuncAttributeMaxDynamicSharedMemorySize, dyn_smem);

    // 1. value = ehs @ w_value^T + b_value   (tf32 TC, cp.async pipeline)
    gemm_tf32_nt<<<MVAL / 128, 256, dyn_smem>>>(ehs, w_value, b_value, pval, MVAL);
    // 2. fused offsets+attn projections (N=288)
    gemm_dual<<<dim3(5, (BQ + BM - 1) / BM), 256>>>(hs, w_off, b_off,
                                                    w_attn, b_attn, poa,
                                                    BQ, 288, DM);
    // 3. softmax + bilinear sampling + weighted sum
    msda_sample2<<<BQ, 256>>>(pval, poa, refp, pmsda);
    // 4. out = msda @ w_out^T + b_out
    gemm_tf32_nt<<<(BQ + 127) / 128, 256, dyn_smem>>>(pmsda, w_out, b_out, out, BQ);
}

// round 6
// speedup vs baseline: 1.2548x; 1.2197x over previous
#include <cuda_runtime.h>
#include <cuda_fp16.h>
#include <cstdint>
#include <math.h>

// Problem constants
#define B_   16
#define Q_   300
#define S_   8400
#define DM   256
#define NH   8
#define HD   32
#define LP_  12
#define BQ   (B_*Q_)          // 4800
#define MVAL (B_*S_)          // 134400

// Scratch (static device globals — no allocation)
__device__ float  g_value[(size_t)MVAL * DM];    // [B,S,256] fp32
__device__ float  g_oa[(size_t)BQ * 288];        // offsets(192)+attn logits(96)
__device__ __half g_ehs_h[(size_t)MVAL * DM];    // encoder states fp16
__device__ __half g_wv_h[DM * DM];               // w_value fp16
__device__ __half g_wo_h[DM * DM];               // w_out fp16
__device__ __half g_msda_h[(size_t)BQ * DM];     // sampled output fp16

// ===========================================================================
// fp32 -> fp16 streaming conversion (16B stores)
// ===========================================================================
__global__ __launch_bounds__(256) void f32_to_f16(
    const float* __restrict__ src, __half* __restrict__ dst, size_t n)
{
    size_t stride = (size_t)gridDim.x * blockDim.x * 8;
    for (size_t i = ((size_t)blockIdx.x * blockDim.x + threadIdx.x) * 8;
         i < n; i += stride) {
        float4 a = *(const float4*)(src + i);
        float4 b = *(const float4*)(src + i + 4);
        __half2 h0 = __floats2half2_rn(a.x, a.y);
        __half2 h1 = __floats2half2_rn(a.z, a.w);
        __half2 h2 = __floats2half2_rn(b.x, b.y);
        __half2 h3 = __floats2half2_rn(b.z, b.w);
        uint4 o;
        o.x = *(uint32_t*)&h0; o.y = *(uint32_t*)&h1;
        o.z = *(uint32_t*)&h2; o.w = *(uint32_t*)&h3;
        *(uint4*)(dst + i) = o;
    }
}

// ===========================================================================
// helpers
// ===========================================================================
__device__ __forceinline__ void mma_m16n8k16_f16(
    float c[4], const uint32_t a[4], const uint32_t b[2])
{
    asm volatile(
        "mma.sync.aligned.m16n8k16.row.col.f32.f16.f16.f32 "
        "{%0,%1,%2,%3}, {%4,%5,%6,%7}, {%8,%9}, {%0,%1,%2,%3};"
        : "+f"(c[0]), "+f"(c[1]), "+f"(c[2]), "+f"(c[3])
        : "r"(a[0]), "r"(a[1]), "r"(a[2]), "r"(a[3]),
          "r"(b[0]), "r"(b[1]));
}
__device__ __forceinline__ void cp_async16(uint32_t dst, const void* src, bool valid) {
    int sz = valid ? 16 : 0;
    asm volatile("cp.async.cg.shared.global [%0], [%1], 16, %2;"
                 :: "r"(dst), "l"(src), "r"(sz));
}
#define CP_COMMIT()  asm volatile("cp.async.commit_group;" ::: "memory")
#define CP_WAIT(N)   asm volatile("cp.async.wait_group %0;" :: "n"(N) : "memory")

// ===========================================================================
// fp16 GEMM (fp32 accum): C[M,256] = A[M,256] @ W[256,256]^T + bias
// CTA tile 128x256, 8 warps (4m x 2n), warp tile 32x128.
// BK=32 halves, 4-stage cp.async. Rows padded to 20 words (16 data + 4):
// conflict-free half2 fragment LDS (grp*20+tig covers all 32 banks).
// ===========================================================================
#define GK      256
#define HBK     32
#define HNCH    (GK / HBK)      // 8 chunks
#define PADH    20              // 32-bit words per row
#define HAW     (128 * PADH)    // 2560 words
#define HBW     (256 * PADH)    // 5120 words
#define HSTAGEW (HAW + HBW)     // 7680 words = 30720 B
#define HNSTAGE 4

__global__ __launch_bounds__(256, 1) void gemm_f16_nt(
    const __half* __restrict__ A, const __half* __restrict__ W,
    const float* __restrict__ bias, float* __restrict__ C, int M)
{
    extern __shared__ uint32_t sm[];

    const int tid  = threadIdx.x;
    const int wid  = tid >> 5;
    const int lane = tid & 31;
    const int grp  = lane >> 2;        // 0..7
    const int tig  = lane & 3;         // 0..3

    const int wm = (wid & 3) * 32;     // warp m offset
    const int wn = (wid >> 2) * 128;   // warp n offset
    const int m0 = blockIdx.x * 128;

    const uint32_t smem_u32 = (uint32_t)__cvta_generic_to_shared(sm);

    float acc[2][16][4];
#pragma unroll
    for (int i = 0; i < 2; i++)
#pragma unroll
        for (int j = 0; j < 16; j++)
#pragma unroll
            for (int l = 0; l < 4; l++) acc[i][j][l] = 0.f;

    // cp.async issue for chunk c into stage s. Each row = 32 halves = 4x16B.
    auto issue = [&](int c, int s) {
        const uint32_t abase = smem_u32 + (uint32_t)(s * HSTAGEW) * 4u;
        const uint32_t bbase = abase + (uint32_t)HAW * 4u;
        const int k0 = c * HBK;
        // A: 128 rows x 4 chunks = 512, 2 per thread
#pragma unroll
        for (int it = 0; it < 2; ++it) {
            int idx = tid + it * 256;
            int row = idx >> 2, col = idx & 3;
            bool v = (m0 + row) < M;
            const __half* src = A + (size_t)(m0 + row) * GK + k0 + col * 8;
            cp_async16(abase + (uint32_t)(row * PADH + col * 4) * 4u, src, v);
        }
        // B: 256 rows x 4 = 1024, 4 per thread
#pragma unroll
        for (int it = 0; it < 4; ++it) {
            int idx = tid + it * 256;
            int row = idx >> 2, col = idx & 3;
            const __half* src = W + (size_t)row * GK + k0 + col * 8;
            cp_async16(bbase + (uint32_t)(row * PADH + col * 4) * 4u, src, true);
        }
        CP_COMMIT();
    };

    issue(0, 0);
    issue(1, 1);
    issue(2, 2);

    for (int c = 0; c < HNCH; ++c) {
        CP_WAIT(2);
        __syncthreads();

        if (c + 3 < HNCH) issue(c + 3, (c + 3) & 3);
        else CP_COMMIT();

        const uint32_t* sA = sm + (c & 3) * HSTAGEW;
        const uint32_t* sB = sA + HAW;

#pragma unroll
        for (int kk = 0; kk < 2; ++kk) {
            const int kb = kk * 8 + tig;       // word offset within row
            uint32_t af[2][4];
#pragma unroll
            for (int mf = 0; mf < 2; ++mf) {
                const int m = wm + mf * 16 + grp;
                af[mf][0] = sA[m * PADH + kb];
                af[mf][1] = sA[(m + 8) * PADH + kb];
                af[mf][2] = sA[m * PADH + kb + 4];
                af[mf][3] = sA[(m + 8) * PADH + kb + 4];
            }
#pragma unroll
            for (int nf = 0; nf < 16; ++nf) {
                const int n = wn + nf * 8 + grp;
                uint32_t bf[2];
                bf[0] = sB[n * PADH + kb];
                bf[1] = sB[n * PADH + kb + 4];
#pragma unroll
                for (int mf = 0; mf < 2; ++mf)
                    mma_m16n8k16_f16(acc[mf][nf], af[mf], bf);
            }
        }
        // no trailing sync needed: stage (c+3)&3 == (c-1)&3 was fully
        // consumed before the barrier at the top of this iteration.
    }

    // ---- epilogue ----
#pragma unroll
    for (int mf = 0; mf < 2; ++mf) {
        const int mlo = m0 + wm + mf * 16 + grp;
#pragma unroll
        for (int nf = 0; nf < 16; ++nf) {
            const int col = wn + nf * 8 + 2 * tig;
            const float bx = __ldg(&bias[col]);
            const float by = __ldg(&bias[col + 1]);
            if (mlo < M) {
                float2 v = make_float2(acc[mf][nf][0] + bx, acc[mf][nf][1] + by);
                *(float2*)(C + (size_t)mlo * DM + col) = v;
            }
            if (mlo + 8 < M) {
                float2 v = make_float2(acc[mf][nf][2] + bx, acc[mf][nf][3] + by);
                *(float2*)(C + (size_t)(mlo + 8) * DM + col) = v;
            }
        }
    }
}

// ---------------------------------------------------------------------------
// Fused offsets+attn projection (fp32 SIMT): C[M,288]
// ---------------------------------------------------------------------------
#define BM 128
#define BN 64
#define BK 16
#define TM 8
#define TN 4

__global__ __launch_bounds__(256) void gemm_dual(
    const float* __restrict__ A,
    const float* __restrict__ Woff, const float* __restrict__ boff,
    const float* __restrict__ Wattn, const float* __restrict__ battn,
    float* __restrict__ C, int M, int N, int K)
{
    __shared__ float As[BK][BM + 4];
    __shared__ float Bs[BK][BN];

    const int tx = threadIdx.x & 15;
    const int ty = threadIdx.x >> 4;
    const int bm = blockIdx.y * BM;
    const int bn = blockIdx.x * BN;

    float acc[TM][TN];
#pragma unroll
    for (int i = 0; i < TM; i++)
#pragma unroll
        for (int j = 0; j < TN; j++) acc[i][j] = 0.f;

    for (int k0 = 0; k0 < K; k0 += BK) {
#pragma unroll
        for (int t = 0; t < (BM * BK) / 256; ++t) {
            int i = threadIdx.x + t * 256;
            int m = i / BK, k = i % BK;
            float v = 0.f;
            if (bm + m < M) v = A[(size_t)(bm + m) * K + k0 + k];
            As[k][m] = v;
        }
#pragma unroll
        for (int t = 0; t < (BN * BK) / 256; ++t) {
            int i = threadIdx.x + t * 256;
            int n = i / BK, k = i % BK;
            int ng = bn + n;
            float v = 0.f;
            if (ng < N) {
                const float* wr = (ng < 192) ? (Woff + (size_t)ng * K)
                                             : (Wattn + (size_t)(ng - 192) * K);
                v = wr[k0 + k];
            }
            Bs[k][n] = v;
        }
        __syncthreads();

#pragma unroll
        for (int k = 0; k < BK; ++k) {
            float a[TM], b[TN];
#pragma unroll
            for (int i = 0; i < TM; i++) a[i] = As[k][ty * TM + i];
#pragma unroll
            for (int j = 0; j < TN; j++) b[j] = Bs[k][tx * TN + j];
#pragma unroll
            for (int i = 0; i < TM; i++)
#pragma unroll
                for (int j = 0; j < TN; j++) acc[i][j] += a[i] * b[j];
        }
        __syncthreads();
    }

#pragma unroll
    for (int i = 0; i < TM; i++) {
        int m = bm + ty * TM + i;
        if (m >= M) continue;
#pragma unroll
        for (int j = 0; j < TN; j++) {
            int n = bn + tx * TN + j;
            if (n < N) {
                float bia = (n < 192) ? boff[n] : battn[n - 192];
                C[(size_t)m * N + n] = acc[i][j] + bia;
            }
        }
    }
}

// ---------------------------------------------------------------------------
// Sampling kernel: block per (b,q). Output written as fp16 (feeds out-proj).
// ---------------------------------------------------------------------------
__global__ __launch_bounds__(256) void msda_sample2(
    const float* __restrict__ value,
    const float* __restrict__ oa,
    const float* __restrict__ refp,
    __half* __restrict__ out)
{
    __shared__ float  s_logit[96];
    __shared__ float2 s_mxinv[8];
    __shared__ int4   s_ofs[96];
    __shared__ float4 s_wts[96];

    const int bq = blockIdx.x;
    const int b  = bq / Q_;
    const int t  = threadIdx.x;

    if (t < 96) s_logit[t] = oa[(size_t)bq * 288 + 192 + t];
    __syncthreads();

    if (t < 8) {
        float mx = -1e30f;
#pragma unroll
        for (int p = 0; p < LP_; p++) mx = fmaxf(mx, s_logit[t * LP_ + p]);
        float s = 0.f;
#pragma unroll
        for (int p = 0; p < LP_; p++) s += __expf(s_logit[t * LP_ + p] - mx);
        s_mxinv[t] = make_float2(mx, 1.f / s);
    }
    __syncthreads();

    if (t < 96) {
        const int h = t / LP_;
        const int p = t - h * LP_;
        const float2 mi = s_mxinv[h];
        const float aw = __expf(s_logit[t] - mi.x) * mi.y;

        const float rx = refp[bq * 4 + 0];
        const float ry = refp[bq * 4 + 1];
        const float rw = refp[bq * 4 + 2];
        const float rh = refp[bq * 4 + 3];

        const float ox = oa[(size_t)bq * 288 + h * 24 + 2 * p + 0];
        const float oy = oa[(size_t)bq * 288 + h * 24 + 2 * p + 1];

        const int lvl   = p >> 2;
        const int Wl    = (lvl == 0) ? 80 : (lvl == 1) ? 40 : 20;
        const int start = (lvl == 0) ? 0 : (lvl == 1) ? 6400 : 8000;

        const float gx = (rx + ox * 0.125f * rw) * (float)Wl - 0.5f;
        const float gy = (ry + oy * 0.125f * rh) * (float)Wl - 0.5f;

        const float x0f = floorf(gx), y0f = floorf(gy);
        const int x0 = (int)x0f, y0 = (int)y0f;
        const int x1 = x0 + 1,  y1 = y0 + 1;
        const float wx1 = gx - x0f, wx0 = 1.f - wx1;
        const float wy1 = gy - y0f, wy0 = 1.f - wy1;

        const bool xv0 = (x0 >= 0) & (x0 < Wl);
        const bool xv1 = (x1 >= 0) & (x1 < Wl);
        const bool yv0 = (y0 >= 0) & (y0 < Wl);
        const bool yv1 = (y1 >= 0) & (y1 < Wl);

        const int x0c = min(max(x0, 0), Wl - 1);
        const int x1c = min(max(x1, 0), Wl - 1);
        const int y0c = min(max(y0, 0), Wl - 1);
        const int y1c = min(max(y1, 0), Wl - 1);

        const int rb = b * S_ + start;
        const int r0 = rb + y0c * Wl;
        const int r1 = rb + y1c * Wl;
        const int hb = h * HD;

        int4 o;
        o.x = (r0 + x0c) * DM + hb;
        o.y = (r0 + x1c) * DM + hb;
        o.z = (r1 + x0c) * DM + hb;
        o.w = (r1 + x1c) * DM + hb;

        float4 w;
        w.x = aw * wx0 * wy0 * (float)(xv0 & yv0);
        w.y = aw * wx1 * wy0 * (float)(xv1 & yv0);
        w.z = aw * wx0 * wy1 * (float)(xv0 & yv1);
        w.w = aw * wx1 * wy1 * (float)(xv1 & yv1);

        s_ofs[t] = o;
        s_wts[t] = w;
    }
    __syncthreads();

    const int h    = t >> 5;
    const int lane = t & 31;
    float acc = 0.f;
#pragma unroll
    for (int p = 0; p < LP_; p++) {
        const int4   o = s_ofs[h * LP_ + p];
        const float4 w = s_wts[h * LP_ + p];
        acc += w.x * __ldg(&value[o.x + lane]);
        acc += w.y * __ldg(&value[o.y + lane]);
        acc += w.z * __ldg(&value[o.z + lane]);
        acc += w.w * __ldg(&value[o.w + lane]);
    }
    out[(size_t)bq * DM + h * HD + lane] = __float2half_rn(acc);
}

// ---------------------------------------------------------------------------
extern "C" void kernel_launch(void* const* d_in, const int* in_sizes, int n_in,
                              void* d_out, int out_size)
{
    const float* hs      = (const float*)d_in[0];
    const float* ehs     = (const float*)d_in[1];
    const float* refp    = (const float*)d_in[2];
    const float* w_value = (const float*)d_in[3];
    const float* b_value = (const float*)d_in[4];
    const float* w_off   = (const float*)d_in[5];
    const float* b_off   = (const float*)d_in[6];
    const float* w_attn  = (const float*)d_in[7];
    const float* b_attn  = (const float*)d_in[8];
    const float* w_out   = (const float*)d_in[9];
    const float* b_out   = (const float*)d_in[10];
    float* out = (float*)d_out;

    float  *pval, *poa;
    __half *pehs, *pwv, *pwo, *pmsda;
    cudaGetSymbolAddress((void**)&pval,  g_value);
    cudaGetSymbolAddress((void**)&poa,   g_oa);
    cudaGetSymbolAddress((void**)&pehs,  g_ehs_h);
    cudaGetSymbolAddress((void**)&pwv,   g_wv_h);
    cudaGetSymbolAddress((void**)&pwo,   g_wo_h);
    cudaGetSymbolAddress((void**)&pmsda, g_msda_h);

    const int dyn_smem = HNSTAGE * HSTAGEW * 4;   // 122880 bytes
    cudaFuncSetAttribute(gemm_f16_nt,
                         cudaFuncAttributeMaxDynamicSharedMemorySize, dyn_smem);

    // 0. fp32 -> fp16 conversions
    f32_to_f16<<<2048, 256>>>(ehs, pehs, (size_t)MVAL * DM);
    f32_to_f16<<<64, 256>>>(w_value, pwv, (size_t)DM * DM);
    f32_to_f16<<<64, 256>>>(w_out, pwo, (size_t)DM * DM);

    // 1. value = ehs @ w_value^T + b_value   (fp16 TC, fp32 accum)
    gemm_f16_nt<<<MVAL / 128, 256, dyn_smem>>>(pehs, pwv, b_value, pval, MVAL);
    // 2. fused offsets+attn projections (N=288, fp32 SIMT)
    gemm_dual<<<dim3(5, (BQ + BM - 1) / BM), 256>>>(hs, w_off, b_off,
                                                    w_attn, b_attn, poa,
                                                    BQ, 288, DM);
    // 3. softmax + bilinear sampling + weighted sum (writes fp16)
    msda_sample2<<<BQ, 256>>>(pval, poa, refp, pmsda);
    // 4. out = msda @ w_out^T + b_out   (fp16 TC)
    gemm_f16_nt<<<(BQ + 127) / 128, 256, dyn_smem>>>(pmsda, pwo, b_out, out, BQ);
}

// round 7
// speedup vs baseline: 1.4118x; 1.1252x over previous
#include <cuda_runtime.h>
#include <cuda_fp16.h>
#include <cstdint>
#include <math.h>

// Problem constants
#define B_   16
#define Q_   300
#define S_   8400
#define DM   256
#define NH   8
#define HD   32
#define LP_  12
#define BQ   (B_*Q_)          // 4800
#define MVAL (B_*S_)          // 134400

// Scratch (static device globals — no allocation)
__device__ float  g_value[(size_t)MVAL * DM];    // [B,S,256] fp32
__device__ float  g_oa[(size_t)BQ * 288];        // offsets(192)+attn logits(96)
__device__ float  g_msda[(size_t)BQ * DM];       // sampled output fp32
__device__ __half g_wv_h[DM * DM];               // w_value fp16
__device__ __half g_wo_h[DM * DM];               // w_out fp16

// ===========================================================================
// fp32 -> fp16 conversion (weights only, tiny)
// ===========================================================================
__global__ __launch_bounds__(256) void f32_to_f16(
    const float* __restrict__ src, __half* __restrict__ dst, size_t n)
{
    size_t stride = (size_t)gridDim.x * blockDim.x * 8;
    for (size_t i = ((size_t)blockIdx.x * blockDim.x + threadIdx.x) * 8;
         i < n; i += stride) {
        float4 a = *(const float4*)(src + i);
        float4 b = *(const float4*)(src + i + 4);
        __half2 h0 = __floats2half2_rn(a.x, a.y);
        __half2 h1 = __floats2half2_rn(a.z, a.w);
        __half2 h2 = __floats2half2_rn(b.x, b.y);
        __half2 h3 = __floats2half2_rn(b.z, b.w);
        uint4 o;
        o.x = *(uint32_t*)&h0; o.y = *(uint32_t*)&h1;
        o.z = *(uint32_t*)&h2; o.w = *(uint32_t*)&h3;
        *(uint4*)(dst + i) = o;
    }
}

// ===========================================================================
// helpers
// ===========================================================================
__device__ __forceinline__ void mma_m16n8k16_f16(
    float c[4], const uint32_t a[4], const uint32_t b[2])
{
    asm volatile(
        "mma.sync.aligned.m16n8k16.row.col.f32.f16.f16.f32 "
        "{%0,%1,%2,%3}, {%4,%5,%6,%7}, {%8,%9}, {%0,%1,%2,%3};"
        : "+f"(c[0]), "+f"(c[1]), "+f"(c[2]), "+f"(c[3])
        : "r"(a[0]), "r"(a[1]), "r"(a[2]), "r"(a[3]),
          "r"(b[0]), "r"(b[1]));
}
__device__ __forceinline__ uint32_t pack_f16x2(float lo, float hi) {
    uint32_t r;
    asm("cvt.rn.f16x2.f32 %0, %1, %2;" : "=r"(r) : "f"(hi), "f"(lo));
    return r;
}
__device__ __forceinline__ void cp_async16(uint32_t dst, const void* src, bool valid) {
    int sz = valid ? 16 : 0;
    asm volatile("cp.async.cg.shared.global [%0], [%1], 16, %2;"
                 :: "r"(dst), "l"(src), "r"(sz));
}
#define CP_COMMIT()  asm volatile("cp.async.commit_group;" ::: "memory")
#define CP_WAIT(N)   asm volatile("cp.async.wait_group %0;" :: "n"(N) : "memory")

// ===========================================================================
// Mixed GEMM: C[M,256] = f16(A_f32[M,256]) @ W_f16[256,256]^T + bias
// A loaded fp32 via cp.async, converted to f16 at fragment load (cvt.f16x2).
// CTA tile 64x256, 8 warps (2m x 4n), warp tile 32x64, 2 CTAs/SM.
// BK=32, 3-stage cp.async pipeline. Stage = A(64x40w fp32) + B(256x20w f16).
// ===========================================================================
#define GK      256
#define CBK     32
#define CNCH    (GK / CBK)      // 8 chunks
#define PADA    40              // fp32 words per A row (32 data + 8 pad)
#define PADB    20              // words per B row (16 data + 4 pad)
#define CAW     (64 * PADA)     // 2560 words
#define CBW     (256 * PADB)    // 5120 words
#define CSTAGEW (CAW + CBW)     // 7680 words = 30720 B
#define CNSTAGE 3

__global__ __launch_bounds__(256, 2) void gemm_a32w16(
    const float* __restrict__ A, const __half* __restrict__ W,
    const float* __restrict__ bias, float* __restrict__ C, int M)
{
    extern __shared__ uint32_t sm[];

    const int tid  = threadIdx.x;
    const int wid  = tid >> 5;
    const int lane = tid & 31;
    const int grp  = lane >> 2;        // 0..7
    const int tig  = lane & 3;         // 0..3

    const int wm = (wid & 1) * 32;     // warp m offset (2 groups)
    const int wn = (wid >> 1) * 64;    // warp n offset (4 groups)
    const int m0 = blockIdx.x * 64;

    const uint32_t smem_u32 = (uint32_t)__cvta_generic_to_shared(sm);

    float acc[2][8][4];
#pragma unroll
    for (int i = 0; i < 2; i++)
#pragma unroll
        for (int j = 0; j < 8; j++)
#pragma unroll
            for (int l = 0; l < 4; l++) acc[i][j][l] = 0.f;

    // cp.async issue for chunk c into stage s
    auto issue = [&](int c, int s) {
        const uint32_t abase = smem_u32 + (uint32_t)(s * CSTAGEW) * 4u;
        const uint32_t bbase = abase + (uint32_t)CAW * 4u;
        const int k0 = c * CBK;
        // A fp32: 64 rows x 8 16B-chunks = 512, 2 per thread
#pragma unroll
        for (int it = 0; it < 2; ++it) {
            int idx = tid + it * 256;
            int row = idx >> 3, col = idx & 7;
            bool v = (m0 + row) < M;
            const float* src = A + (size_t)(m0 + row) * GK + k0 + col * 4;
            cp_async16(abase + (uint32_t)(row * PADA + col * 4) * 4u, src, v);
        }
        // B f16: 256 rows x 4 16B-chunks = 1024, 4 per thread
#pragma unroll
        for (int it = 0; it < 4; ++it) {
            int idx = tid + it * 256;
            int row = idx >> 2, col = idx & 3;
            const __half* src = W + (size_t)row * GK + k0 + col * 8;
            cp_async16(bbase + (uint32_t)(row * PADB + col * 4) * 4u, src, true);
        }
        CP_COMMIT();
    };

    issue(0, 0);
    issue(1, 1);

    for (int c = 0; c < CNCH; ++c) {
        CP_WAIT(1);           // chunk c resident
        __syncthreads();

        if (c + 2 < CNCH) issue(c + 2, (c + 2) % CNSTAGE);
        else CP_COMMIT();

        const uint32_t* sAw = sm + (c % CNSTAGE) * CSTAGEW;
        const float*    sA  = (const float*)sAw;
        const uint32_t* sB  = sAw + CAW;

#pragma unroll
        for (int kk = 0; kk < 2; ++kk) {
            const int ka = kk * 16 + 2 * tig;  // fp32 word offset in A row
            const int kb = kk * 8 + tig;       // packed word offset in B row
            uint32_t af[2][4];
#pragma unroll
            for (int mf = 0; mf < 2; ++mf) {
                const int m = wm + mf * 16 + grp;
                float2 a0 = *(const float2*)(sA + m * PADA + ka);
                float2 a1 = *(const float2*)(sA + (m + 8) * PADA + ka);
                float2 a2 = *(const float2*)(sA + m * PADA + ka + 8);
                float2 a3 = *(const float2*)(sA + (m + 8) * PADA + ka + 8);
                af[mf][0] = pack_f16x2(a0.x, a0.y);
                af[mf][1] = pack_f16x2(a1.x, a1.y);
                af[mf][2] = pack_f16x2(a2.x, a2.y);
                af[mf][3] = pack_f16x2(a3.x, a3.y);
            }
#pragma unroll
            for (int nf = 0; nf < 8; ++nf) {
                const int n = wn + nf * 8 + grp;
                uint32_t bf[2];
                bf[0] = sB[n * PADB + kb];
                bf[1] = sB[n * PADB + kb + 4];
#pragma unroll
                for (int mf = 0; mf < 2; ++mf)
                    mma_m16n8k16_f16(acc[mf][nf], af[mf], bf);
            }
        }
        // stage reused by chunk c+2 equals stage of chunk c-1, whose compute
        // finished before this iteration's top barrier -> no trailing sync.
    }

    // ---- epilogue ----
#pragma unroll
    for (int mf = 0; mf < 2; ++mf) {
        const int mlo = m0 + wm + mf * 16 + grp;
#pragma unroll
        for (int nf = 0; nf < 8; ++nf) {
            const int col = wn + nf * 8 + 2 * tig;
            const float bx = __ldg(&bias[col]);
            const float by = __ldg(&bias[col + 1]);
            if (mlo < M) {
                float2 v = make_float2(acc[mf][nf][0] + bx, acc[mf][nf][1] + by);
                *(float2*)(C + (size_t)mlo * DM + col) = v;
            }
            if (mlo + 8 < M) {
                float2 v = make_float2(acc[mf][nf][2] + bx, acc[mf][nf][3] + by);
                *(float2*)(C + (size_t)(mlo + 8) * DM + col) = v;
            }
        }
    }
}

// ---------------------------------------------------------------------------
// Fused offsets+attn projection (fp32 SIMT): C[M,288]
// ---------------------------------------------------------------------------
#define BM 128
#define BN 64
#define BK 16
#define TM 8
#define TN 4

__global__ __launch_bounds__(256) void gemm_dual(
    const float* __restrict__ A,
    const float* __restrict__ Woff, const float* __restrict__ boff,
    const float* __restrict__ Wattn, const float* __restrict__ battn,
    float* __restrict__ C, int M, int N, int K)
{
    __shared__ float As[BK][BM + 4];
    __shared__ float Bs[BK][BN];

    const int tx = threadIdx.x & 15;
    const int ty = threadIdx.x >> 4;
    const int bm = blockIdx.y * BM;
    const int bn = blockIdx.x * BN;

    float acc[TM][TN];
#pragma unroll
    for (int i = 0; i < TM; i++)
#pragma unroll
        for (int j = 0; j < TN; j++) acc[i][j] = 0.f;

    for (int k0 = 0; k0 < K; k0 += BK) {
#pragma unroll
        for (int t = 0; t < (BM * BK) / 256; ++t) {
            int i = threadIdx.x + t * 256;
            int m = i / BK, k = i % BK;
            float v = 0.f;
            if (bm + m < M) v = A[(size_t)(bm + m) * K + k0 + k];
            As[k][m] = v;
        }
#pragma unroll
        for (int t = 0; t < (BN * BK) / 256; ++t) {
            int i = threadIdx.x + t * 256;
            int n = i / BK, k = i % BK;
            int ng = bn + n;
            float v = 0.f;
            if (ng < N) {
                const float* wr = (ng < 192) ? (Woff + (size_t)ng * K)
                                             : (Wattn + (size_t)(ng - 192) * K);
                v = wr[k0 + k];
            }
            Bs[k][n] = v;
        }
        __syncthreads();

#pragma unroll
        for (int k = 0; k < BK; ++k) {
            float a[TM], b[TN];
#pragma unroll
            for (int i = 0; i < TM; i++) a[i] = As[k][ty * TM + i];
#pragma unroll
            for (int j = 0; j < TN; j++) b[j] = Bs[k][tx * TN + j];
#pragma unroll
            for (int i = 0; i < TM; i++)
#pragma unroll
                for (int j = 0; j < TN; j++) acc[i][j] += a[i] * b[j];
        }
        __syncthreads();
    }

#pragma unroll
    for (int i = 0; i < TM; i++) {
        int m = bm + ty * TM + i;
        if (m >= M) continue;
#pragma unroll
        for (int j = 0; j < TN; j++) {
            int n = bn + tx * TN + j;
            if (n < N) {
                float bia = (n < 192) ? boff[n] : battn[n - 192];
                C[(size_t)m * N + n] = acc[i][j] + bia;
            }
        }
    }
}

// ---------------------------------------------------------------------------
// Sampling kernel: block per (b,q).
// ---------------------------------------------------------------------------
__global__ __launch_bounds__(256) void msda_sample2(
    const float* __restrict__ value,
    const float* __restrict__ oa,
    const float* __restrict__ refp,
    float* __restrict__ out)
{
    __shared__ float  s_logit[96];
    __shared__ float2 s_mxinv[8];
    __shared__ int4   s_ofs[96];
    __shared__ float4 s_wts[96];

    const int bq = blockIdx.x;
    const int b  = bq / Q_;
    const int t  = threadIdx.x;

    if (t < 96) s_logit[t] = oa[(size_t)bq * 288 + 192 + t];
    __syncthreads();

    if (t < 8) {
        float mx = -1e30f;
#pragma unroll
        for (int p = 0; p < LP_; p++) mx = fmaxf(mx, s_logit[t * LP_ + p]);
        float s = 0.f;
#pragma unroll
        for (int p = 0; p < LP_; p++) s += __expf(s_logit[t * LP_ + p] - mx);
        s_mxinv[t] = make_float2(mx, 1.f / s);
    }
    __syncthreads();

    if (t < 96) {
        const int h = t / LP_;
        const int p = t - h * LP_;
        const float2 mi = s_mxinv[h];
        const float aw = __expf(s_logit[t] - mi.x) * mi.y;

        const float rx = refp[bq * 4 + 0];
        const float ry = refp[bq * 4 + 1];
        const float rw = refp[bq * 4 + 2];
        const float rh = refp[bq * 4 + 3];

        const float ox = oa[(size_t)bq * 288 + h * 24 + 2 * p + 0];
        const float oy = oa[(size_t)bq * 288 + h * 24 + 2 * p + 1];

        const int lvl   = p >> 2;
        const int Wl    = (lvl == 0) ? 80 : (lvl == 1) ? 40 : 20;
        const int start = (lvl == 0) ? 0 : (lvl == 1) ? 6400 : 8000;

        const float gx = (rx + ox * 0.125f * rw) * (float)Wl - 0.5f;
        const float gy = (ry + oy * 0.125f * rh) * (float)Wl - 0.5f;

        const float x0f = floorf(gx), y0f = floorf(gy);
        const int x0 = (int)x0f, y0 = (int)y0f;
        const int x1 = x0 + 1,  y1 = y0 + 1;
        const float wx1 = gx - x0f, wx0 = 1.f - wx1;
        const float wy1 = gy - y0f, wy0 = 1.f - wy1;

        const bool xv0 = (x0 >= 0) & (x0 < Wl);
        const bool xv1 = (x1 >= 0) & (x1 < Wl);
        const bool yv0 = (y0 >= 0) & (y0 < Wl);
        const bool yv1 = (y1 >= 0) & (y1 < Wl);

        const int x0c = min(max(x0, 0), Wl - 1);
        const int x1c = min(max(x1, 0), Wl - 1);
        const int y0c = min(max(y0, 0), Wl - 1);
        const int y1c = min(max(y1, 0), Wl - 1);

        const int rb = b * S_ + start;
        const int r0 = rb + y0c * Wl;
        const int r1 = rb + y1c * Wl;
        const int hb = h * HD;

        int4 o;
        o.x = (r0 + x0c) * DM + hb;
        o.y = (r0 + x1c) * DM + hb;
        o.z = (r1 + x0c) * DM + hb;
        o.w = (r1 + x1c) * DM + hb;

        float4 w;
        w.x = aw * wx0 * wy0 * (float)(xv0 & yv0);
        w.y = aw * wx1 * wy0 * (float)(xv1 & yv0);
        w.z = aw * wx0 * wy1 * (float)(xv0 & yv1);
        w.w = aw * wx1 * wy1 * (float)(xv1 & yv1);

        s_ofs[t] = o;
        s_wts[t] = w;
    }
    __syncthreads();

    const int h    = t >> 5;
    const int lane = t & 31;
    float acc = 0.f;
#pragma unroll
    for (int p = 0; p < LP_; p++) {
        const int4   o = s_ofs[h * LP_ + p];
        const float4 w = s_wts[h * LP_ + p];
        acc += w.x * __ldg(&value[o.x + lane]);
        acc += w.y * __ldg(&value[o.y + lane]);
        acc += w.z * __ldg(&value[o.z + lane]);
        acc += w.w * __ldg(&value[o.w + lane]);
    }
    out[(size_t)bq * DM + h * HD + lane] = acc;
}

// ---------------------------------------------------------------------------
extern "C" void kernel_launch(void* const* d_in, const int* in_sizes, int n_in,
                              void* d_out, int out_size)
{
    const float* hs      = (const float*)d_in[0];
    const float* ehs     = (const float*)d_in[1];
    const float* refp    = (const float*)d_in[2];
    const float* w_value = (const float*)d_in[3];
    const float* b_value = (const float*)d_in[4];
    const float* w_off   = (const float*)d_in[5];
    const float* b_off   = (const float*)d_in[6];
    const float* w_attn  = (const float*)d_in[7];
    const float* b_attn  = (const float*)d_in[8];
    const float* w_out   = (const float*)d_in[9];
    const float* b_out   = (const float*)d_in[10];
    float* out = (float*)d_out;

    float  *pval, *poa, *pmsda;
    __half *pwv, *pwo;
    cudaGetSymbolAddress((void**)&pval,  g_value);
    cudaGetSymbolAddress((void**)&poa,   g_oa);
    cudaGetSymbolAddress((void**)&pmsda, g_msda);
    cudaGetSymbolAddress((void**)&pwv,   g_wv_h);
    cudaGetSymbolAddress((void**)&pwo,   g_wo_h);

    const int dyn_smem = CNSTAGE * CSTAGEW * 4;   // 92160 bytes
    cudaFuncSetAttribute(gemm_a32w16,
                         cudaFuncAttributeMaxDynamicSharedMemorySize, dyn_smem);

    // 0. weight conversions (tiny)
    f32_to_f16<<<64, 256>>>(w_value, pwv, (size_t)DM * DM);
    f32_to_f16<<<64, 256>>>(w_out, pwo, (size_t)DM * DM);

    // 1. value = ehs @ w_value^T + b_value   (A fp32 direct, W fp16)
    gemm_a32w16<<<MVAL / 64, 256, dyn_smem>>>(ehs, pwv, b_value, pval, MVAL);
    // 2. fused offsets+attn projections
    gemm_dual<<<dim3(5, (BQ + BM - 1) / BM), 256>>>(hs, w_off, b_off,
                                                    w_attn, b_attn, poa,
                                                    BQ, 288, DM);
    // 3. softmax + bilinear sampling + weighted sum
    msda_sample2<<<BQ, 256>>>(pval, poa, refp, pmsda);
    // 4. out = msda @ w_out^T + b_out
    gemm_a32w16<<<BQ / 64, 256, dyn_smem>>>(pmsda, pwo, b_out, out, BQ);
}

// round 8
// speedup vs baseline: 1.6641x; 1.1787x over previous
#include <cuda_runtime.h>
#include <cuda_fp16.h>
#include <cstdint>
#include <math.h>

// Problem constants
#define B_   16
#define Q_   300
#define S_   8400
#define DM   256
#define NH   8
#define HD   32
#define LP_  12
#define BQ   (B_*Q_)          // 4800
#define MVAL (B_*S_)          // 134400

// Scratch (static device globals — no allocation)
__device__ float  g_value[(size_t)MVAL * DM];    // [B,S,256] fp32
__device__ float  g_oa[(size_t)BQ * 288];        // offsets(192)+attn logits(96)
__device__ float  g_msda[(size_t)BQ * DM];       // sampled output fp32
__device__ __half g_wv_h[DM * DM];               // w_value fp16
__device__ __half g_wo_h[DM * DM];               // w_out fp16
__device__ __half g_woa_hi[320 * DM];            // fused off+attn W, fp16 hi
__device__ __half g_woa_lo[320 * DM];            // fused off+attn W, fp16 lo
__device__ float  g_boa[320];                    // fused bias

// ===========================================================================
// weight prep kernels (tiny, one-time per launch)
// ===========================================================================
__global__ __launch_bounds__(256) void f32_to_f16(
    const float* __restrict__ src, __half* __restrict__ dst, size_t n)
{
    size_t stride = (size_t)gridDim.x * blockDim.x * 8;
    for (size_t i = ((size_t)blockIdx.x * blockDim.x + threadIdx.x) * 8;
         i < n; i += stride) {
        float4 a = *(const float4*)(src + i);
        float4 b = *(const float4*)(src + i + 4);
        __half2 h0 = __floats2half2_rn(a.x, a.y);
        __half2 h1 = __floats2half2_rn(a.z, a.w);
        __half2 h2 = __floats2half2_rn(b.x, b.y);
        __half2 h3 = __floats2half2_rn(b.z, b.w);
        uint4 o;
        o.x = *(uint32_t*)&h0; o.y = *(uint32_t*)&h1;
        o.z = *(uint32_t*)&h2; o.w = *(uint32_t*)&h3;
        *(uint4*)(dst + i) = o;
    }
}

// Pack Woff(192)+Wattn(96)+zeros(32) rows into hi/lo fp16 split + bias.
__global__ __launch_bounds__(256) void pack_split_woa(
    const float* __restrict__ Woff,  const float* __restrict__ boff,
    const float* __restrict__ Wattn, const float* __restrict__ battn,
    __half* __restrict__ Whi, __half* __restrict__ Wlo,
    float* __restrict__ bdst)
{
    const int r = blockIdx.x;      // 0..319
    const int k = threadIdx.x;     // 0..255
    float v = 0.f;
    if (r < 192)      v = Woff[r * DM + k];
    else if (r < 288) v = Wattn[(r - 192) * DM + k];
    __half h = __float2half_rn(v);
    Whi[r * DM + k] = h;
    Wlo[r * DM + k] = __float2half_rn(v - __half2float(h));
    if (k == 0) bdst[r] = (r < 192) ? boff[r] : (r < 288 ? battn[r - 192] : 0.f);
}

// ===========================================================================
// helpers
// ===========================================================================
__device__ __forceinline__ void mma_m16n8k16_f16(
    float c[4], const uint32_t a[4], const uint32_t b[2])
{
    asm volatile(
        "mma.sync.aligned.m16n8k16.row.col.f32.f16.f16.f32 "
        "{%0,%1,%2,%3}, {%4,%5,%6,%7}, {%8,%9}, {%0,%1,%2,%3};"
        : "+f"(c[0]), "+f"(c[1]), "+f"(c[2]), "+f"(c[3])
        : "r"(a[0]), "r"(a[1]), "r"(a[2]), "r"(a[3]),
          "r"(b[0]), "r"(b[1]));
}
__device__ __forceinline__ uint32_t pack_f16x2(float lo, float hi) {
    uint32_t r;
    asm("cvt.rn.f16x2.f32 %0, %1, %2;" : "=r"(r) : "f"(hi), "f"(lo));
    return r;
}
__device__ __forceinline__ void cp_async16(uint32_t dst, const void* src, bool valid) {
    int sz = valid ? 16 : 0;
    asm volatile("cp.async.cg.shared.global [%0], [%1], 16, %2;"
                 :: "r"(dst), "l"(src), "r"(sz));
}
#define CP_COMMIT()  asm volatile("cp.async.commit_group;" ::: "memory")
#define CP_WAIT(N)   asm volatile("cp.async.wait_group %0;" :: "n"(N) : "memory")

// ===========================================================================
// Mixed GEMM: C[M,256] = f16(A_f32[M,256]) @ W_f16[256,256]^T + bias
// CTA tile 64x256, 8 warps (2m x 4n), warp tile 32x64, 2 CTAs/SM.
// BK=32, 3-stage cp.async. A kept fp32 in SMEM, cvt at fragment load.
// ===========================================================================
#define GK      256
#define CBK     32
#define CNCH    (GK / CBK)      // 8 chunks
#define PADA    40              // fp32 words per A row
#define PADB    20              // packed f16 words per B row
#define CAW     (64 * PADA)     // 2560 words
#define CBW     (256 * PADB)    // 5120 words
#define CSTAGEW (CAW + CBW)     // 7680 words
#define CNSTAGE 3

__global__ __launch_bounds__(256, 2) void gemm_a32w16(
    const float* __restrict__ A, const __half* __restrict__ W,
    const float* __restrict__ bias, float* __restrict__ C, int M)
{
    extern __shared__ uint32_t sm[];

    const int tid  = threadIdx.x;
    const int wid  = tid >> 5;
    const int lane = tid & 31;
    const int grp  = lane >> 2;
    const int tig  = lane & 3;

    const int wm = (wid & 1) * 32;
    const int wn = (wid >> 1) * 64;
    const int m0 = blockIdx.x * 64;

    const uint32_t smem_u32 = (uint32_t)__cvta_generic_to_shared(sm);

    float acc[2][8][4];
#pragma unroll
    for (int i = 0; i < 2; i++)
#pragma unroll
        for (int j = 0; j < 8; j++)
#pragma unroll
            for (int l = 0; l < 4; l++) acc[i][j][l] = 0.f;

    auto issue = [&](int c, int s) {
        const uint32_t abase = smem_u32 + (uint32_t)(s * CSTAGEW) * 4u;
        const uint32_t bbase = abase + (uint32_t)CAW * 4u;
        const int k0 = c * CBK;
#pragma unroll
        for (int it = 0; it < 2; ++it) {
            int idx = tid + it * 256;
            int row = idx >> 3, col = idx & 7;
            bool v = (m0 + row) < M;
            const float* src = A + (size_t)(m0 + row) * GK + k0 + col * 4;
            cp_async16(abase + (uint32_t)(row * PADA + col * 4) * 4u, src, v);
        }
#pragma unroll
        for (int it = 0; it < 4; ++it) {
            int idx = tid + it * 256;
            int row = idx >> 2, col = idx & 3;
            const __half* src = W + (size_t)row * GK + k0 + col * 8;
            cp_async16(bbase + (uint32_t)(row * PADB + col * 4) * 4u, src, true);
        }
        CP_COMMIT();
    };

    issue(0, 0);
    issue(1, 1);

    for (int c = 0; c < CNCH; ++c) {
        CP_WAIT(1);
        __syncthreads();

        if (c + 2 < CNCH) issue(c + 2, (c + 2) % CNSTAGE);
        else CP_COMMIT();

        const uint32_t* sAw = sm + (c % CNSTAGE) * CSTAGEW;
        const float*    sA  = (const float*)sAw;
        const uint32_t* sB  = sAw + CAW;

#pragma unroll
        for (int kk = 0; kk < 2; ++kk) {
            const int ka = kk * 16 + 2 * tig;
            const int kb = kk * 8 + tig;
            uint32_t af[2][4];
#pragma unroll
            for (int mf = 0; mf < 2; ++mf) {
                const int m = wm + mf * 16 + grp;
                float2 a0 = *(const float2*)(sA + m * PADA + ka);
                float2 a1 = *(const float2*)(sA + (m + 8) * PADA + ka);
                float2 a2 = *(const float2*)(sA + m * PADA + ka + 8);
                float2 a3 = *(const float2*)(sA + (m + 8) * PADA + ka + 8);
                af[mf][0] = pack_f16x2(a0.x, a0.y);
                af[mf][1] = pack_f16x2(a1.x, a1.y);
                af[mf][2] = pack_f16x2(a2.x, a2.y);
                af[mf][3] = pack_f16x2(a3.x, a3.y);
            }
#pragma unroll
            for (int nf = 0; nf < 8; ++nf) {
                const int n = wn + nf * 8 + grp;
                uint32_t bf[2];
                bf[0] = sB[n * PADB + kb];
                bf[1] = sB[n * PADB + kb + 4];
#pragma unroll
                for (int mf = 0; mf < 2; ++mf)
                    mma_m16n8k16_f16(acc[mf][nf], af[mf], bf);
            }
        }
    }

#pragma unroll
    for (int mf = 0; mf < 2; ++mf) {
        const int mlo = m0 + wm + mf * 16 + grp;
#pragma unroll
        for (int nf = 0; nf < 8; ++nf) {
            const int col = wn + nf * 8 + 2 * tig;
            const float bx = __ldg(&bias[col]);
            const float by = __ldg(&bias[col + 1]);
            if (mlo < M) {
                float2 v = make_float2(acc[mf][nf][0] + bx, acc[mf][nf][1] + by);
                *(float2*)(C + (size_t)mlo * DM + col) = v;
            }
            if (mlo + 8 < M) {
                float2 v = make_float2(acc[mf][nf][2] + bx, acc[mf][nf][3] + by);
                *(float2*)(C + (size_t)(mlo + 8) * DM + col) = v;
            }
        }
    }
}

// ===========================================================================
// Split-fp16 TC GEMM for offsets+attn: C[4800,288] = hs @ Woa^T + b
// 3-term compensated fp16: C = Ah*Bh + Ah*Bl + Al*Bh (error ~2e-7).
// N padded to 320. CTA tile 64x320, 8 warps (2m x 4n), warp tile 32x80.
// Grid = 75 CTAs (1/SM). 3-stage cp.async.
// ===========================================================================
#define DAW     (64 * PADA)          // 2560 words
#define DBW     (320 * PADB)         // 6400 words (per hi or lo tile)
#define DSTAGEW (DAW + 2 * DBW)      // 15360 words = 61440 B
#define DNSTAGE 3

__global__ __launch_bounds__(256) void gemm_dual_tc(
    const float* __restrict__ A,
    const __half* __restrict__ Whi, const __half* __restrict__ Wlo,
    const float* __restrict__ bias, float* __restrict__ C, int M)
{
    extern __shared__ uint32_t sm[];

    const int tid  = threadIdx.x;
    const int wid  = tid >> 5;
    const int lane = tid & 31;
    const int grp  = lane >> 2;
    const int tig  = lane & 3;

    const int wm = (wid & 1) * 32;
    const int wn = (wid >> 1) * 80;
    const int m0 = blockIdx.x * 64;

    const uint32_t smem_u32 = (uint32_t)__cvta_generic_to_shared(sm);

    float acc[2][10][4];
#pragma unroll
    for (int i = 0; i < 2; i++)
#pragma unroll
        for (int j = 0; j < 10; j++)
#pragma unroll
            for (int l = 0; l < 4; l++) acc[i][j][l] = 0.f;

    auto issue = [&](int c, int s) {
        const uint32_t abase  = smem_u32 + (uint32_t)(s * DSTAGEW) * 4u;
        const uint32_t bhbase = abase + (uint32_t)DAW * 4u;
        const uint32_t blbase = bhbase + (uint32_t)DBW * 4u;
        const int k0 = c * CBK;
        // A fp32: 64 rows x 8 chunks = 512 -> 2/thread
#pragma unroll
        for (int it = 0; it < 2; ++it) {
            int idx = tid + it * 256;
            int row = idx >> 3, col = idx & 7;
            bool v = (m0 + row) < M;
            const float* src = A + (size_t)(m0 + row) * GK + k0 + col * 4;
            cp_async16(abase + (uint32_t)(row * PADA + col * 4) * 4u, src, v);
        }
        // Bhi/Blo: 320 rows x 4 chunks = 1280 each -> 5/thread each
#pragma unroll
        for (int it = 0; it < 5; ++it) {
            int idx = tid + it * 256;
            int row = idx >> 2, col = idx & 3;
            const __half* srch = Whi + (size_t)row * GK + k0 + col * 8;
            cp_async16(bhbase + (uint32_t)(row * PADB + col * 4) * 4u, srch, true);
        }
#pragma unroll
        for (int it = 0; it < 5; ++it) {
            int idx = tid + it * 256;
            int row = idx >> 2, col = idx & 3;
            const __half* srcl = Wlo + (size_t)row * GK + k0 + col * 8;
            cp_async16(blbase + (uint32_t)(row * PADB + col * 4) * 4u, srcl, true);
        }
        CP_COMMIT();
    };

    issue(0, 0);
    issue(1, 1);

    for (int c = 0; c < CNCH; ++c) {
        CP_WAIT(1);
        __syncthreads();

        if (c + 2 < CNCH) issue(c + 2, (c + 2) % DNSTAGE);
        else CP_COMMIT();

        const uint32_t* sAw = sm + (c % DNSTAGE) * DSTAGEW;
        const float*    sA  = (const float*)sAw;
        const uint32_t* sBh = sAw + DAW;
        const uint32_t* sBl = sBh + DBW;

#pragma unroll
        for (int kk = 0; kk < 2; ++kk) {
            const int ka = kk * 16 + 2 * tig;
            const int kb = kk * 8 + tig;
            uint32_t ah[2][4], al[2][4];
#pragma unroll
            for (int mf = 0; mf < 2; ++mf) {
                const int m = wm + mf * 16 + grp;
                float2 a0 = *(const float2*)(sA + m * PADA + ka);
                float2 a1 = *(const float2*)(sA + (m + 8) * PADA + ka);
                float2 a2 = *(const float2*)(sA + m * PADA + ka + 8);
                float2 a3 = *(const float2*)(sA + (m + 8) * PADA + ka + 8);
#pragma unroll
                for (int q = 0; q < 4; ++q) {
                    float2 av = (q == 0) ? a0 : (q == 1) ? a1 : (q == 2) ? a2 : a3;
                    uint32_t hi = pack_f16x2(av.x, av.y);
                    float2 hf = __half22float2(*(__half2*)&hi);
                    ah[mf][q] = hi;
                    al[mf][q] = pack_f16x2(av.x - hf.x, av.y - hf.y);
                }
            }
#pragma unroll
            for (int nf = 0; nf < 10; ++nf) {
                const int n = wn + nf * 8 + grp;
                uint32_t bh[2], bl[2];
                bh[0] = sBh[n * PADB + kb];
                bh[1] = sBh[n * PADB + kb + 4];
                bl[0] = sBl[n * PADB + kb];
                bl[1] = sBl[n * PADB + kb + 4];
#pragma unroll
                for (int mf = 0; mf < 2; ++mf) {
                    mma_m16n8k16_f16(acc[mf][nf], ah[mf], bh);
                    mma_m16n8k16_f16(acc[mf][nf], ah[mf], bl);
                    mma_m16n8k16_f16(acc[mf][nf], al[mf], bh);
                }
            }
        }
    }

    // epilogue: C stride 288, guard col < 288
#pragma unroll
    for (int mf = 0; mf < 2; ++mf) {
        const int mlo = m0 + wm + mf * 16 + grp;
#pragma unroll
        for (int nf = 0; nf < 10; ++nf) {
            const int col = wn + nf * 8 + 2 * tig;
            if (col >= 288) continue;
            const float bx = __ldg(&bias[col]);
            const float by = __ldg(&bias[col + 1]);
            if (mlo < M) {
                float2 v = make_float2(acc[mf][nf][0] + bx, acc[mf][nf][1] + by);
                *(float2*)(C + (size_t)mlo * 288 + col) = v;
            }
            if (mlo + 8 < M) {
                float2 v = make_float2(acc[mf][nf][2] + bx, acc[mf][nf][3] + by);
                *(float2*)(C + (size_t)(mlo + 8) * 288 + col) = v;
            }
        }
    }
}

// ---------------------------------------------------------------------------
// Sampling kernel: block per (b,q).
// ---------------------------------------------------------------------------
__global__ __launch_bounds__(256) void msda_sample2(
    const float* __restrict__ value,
    const float* __restrict__ oa,
    const float* __restrict__ refp,
    float* __restrict__ out)
{
    __shared__ float  s_logit[96];
    __shared__ float2 s_mxinv[8];
    __shared__ int4   s_ofs[96];
    __shared__ float4 s_wts[96];

    const int bq = blockIdx.x;
    const int b  = bq / Q_;
    const int t  = threadIdx.x;

    if (t < 96) s_logit[t] = oa[(size_t)bq * 288 + 192 + t];
    __syncthreads();

    if (t < 8) {
        float mx = -1e30f;
#pragma unroll
        for (int p = 0; p < LP_; p++) mx = fmaxf(mx, s_logit[t * LP_ + p]);
        float s = 0.f;
#pragma unroll
        for (int p = 0; p < LP_; p++) s += __expf(s_logit[t * LP_ + p] - mx);
        s_mxinv[t] = make_float2(mx, 1.f / s);
    }
    __syncthreads();

    if (t < 96) {
        const int h = t / LP_;
        const int p = t - h * LP_;
        const float2 mi = s_mxinv[h];
        const float aw = __expf(s_logit[t] - mi.x) * mi.y;

        const float rx = refp[bq * 4 + 0];
        const float ry = refp[bq * 4 + 1];
        const float rw = refp[bq * 4 + 2];
        const float rh = refp[bq * 4 + 3];

        const float ox = oa[(size_t)bq * 288 + h * 24 + 2 * p + 0];
        const float oy = oa[(size_t)bq * 288 + h * 24 + 2 * p + 1];

        const int lvl   = p >> 2;
        const int Wl    = (lvl == 0) ? 80 : (lvl == 1) ? 40 : 20;
        const int start = (lvl == 0) ? 0 : (lvl == 1) ? 6400 : 8000;

        const float gx = (rx + ox * 0.125f * rw) * (float)Wl - 0.5f;
        const float gy = (ry + oy * 0.125f * rh) * (float)Wl - 0.5f;

        const float x0f = floorf(gx), y0f = floorf(gy);
        const int x0 = (int)x0f, y0 = (int)y0f;
        const int x1 = x0 + 1,  y1 = y0 + 1;
        const float wx1 = gx - x0f, wx0 = 1.f - wx1;
        const float wy1 = gy - y0f, wy0 = 1.f - wy1;

        const bool xv0 = (x0 >= 0) & (x0 < Wl);
        const bool xv1 = (x1 >= 0) & (x1 < Wl);
        const bool yv0 = (y0 >= 0) & (y0 < Wl);
        const bool yv1 = (y1 >= 0) & (y1 < Wl);

        const int x0c = min(max(x0, 0), Wl - 1);
        const int x1c = min(max(x1, 0), Wl - 1);
        const int y0c = min(max(y0, 0), Wl - 1);
        const int y1c = min(max(y1, 0), Wl - 1);

        const int rb = b * S_ + start;
        const int r0 = rb + y0c * Wl;
        const int r1 = rb + y1c * Wl;
        const int hb = h * HD;

        int4 o;
        o.x = (r0 + x0c) * DM + hb;
        o.y = (r0 + x1c) * DM + hb;
        o.z = (r1 + x0c) * DM + hb;
        o.w = (r1 + x1c) * DM + hb;

        float4 w;
        w.x = aw * wx0 * wy0 * (float)(xv0 & yv0);
        w.y = aw * wx1 * wy0 * (float)(xv1 & yv0);
        w.z = aw * wx0 * wy1 * (float)(xv0 & yv1);
        w.w = aw * wx1 * wy1 * (float)(xv1 & yv1);

        s_ofs[t] = o;
        s_wts[t] = w;
    }
    __syncthreads();

    const int h    = t >> 5;
    const int lane = t & 31;
    float acc = 0.f;
#pragma unroll
    for (int p = 0; p < LP_; p++) {
        const int4   o = s_ofs[h * LP_ + p];
        const float4 w = s_wts[h * LP_ + p];
        acc += w.x * __ldg(&value[o.x + lane]);
        acc += w.y * __ldg(&value[o.y + lane]);
        acc += w.z * __ldg(&value[o.z + lane]);
        acc += w.w * __ldg(&value[o.w + lane]);
    }
    out[(size_t)bq * DM + h * HD + lane] = acc;
}

// ---------------------------------------------------------------------------
extern "C" void kernel_launch(void* const* d_in, const int* in_sizes, int n_in,
                              void* d_out, int out_size)
{
    const float* hs      = (const float*)d_in[0];
    const float* ehs     = (const float*)d_in[1];
    const float* refp    = (const float*)d_in[2];
    const float* w_value = (const float*)d_in[3];
    const float* b_value = (const float*)d_in[4];
    const float* w_off   = (const float*)d_in[5];
    const float* b_off   = (const float*)d_in[6];
    const float* w_attn  = (const float*)d_in[7];
    const float* b_attn  = (const float*)d_in[8];
    const float* w_out   = (const float*)d_in[9];
    const float* b_out   = (const float*)d_in[10];
    float* out = (float*)d_out;

    float  *pval, *poa, *pmsda, *pboa;
    __half *pwv, *pwo, *pwhi, *pwlo;
    cudaGetSymbolAddress((void**)&pval,  g_value);
    cudaGetSymbolAddress((void**)&poa,   g_oa);
    cudaGetSymbolAddress((void**)&pmsda, g_msda);
    cudaGetSymbolAddress((void**)&pwv,   g_wv_h);
    cudaGetSymbolAddress((void**)&pwo,   g_wo_h);
    cudaGetSymbolAddress((void**)&pwhi,  g_woa_hi);
    cudaGetSymbolAddress((void**)&pwlo,  g_woa_lo);
    cudaGetSymbolAddress((void**)&pboa,  g_boa);

    const int smem_val  = CNSTAGE * CSTAGEW * 4;   // 92160 B
    const int smem_dual = DNSTAGE * DSTAGEW * 4;   // 184320 B
    cudaFuncSetAttribute(gemm_a32w16,
                         cudaFuncAttributeMaxDynamicSharedMemorySize, smem_val);
    cudaFuncSetAttribute(gemm_dual_tc,
                         cudaFuncAttributeMaxDynamicSharedMemorySize, smem_dual);

    // 0. weight prep (tiny)
    f32_to_f16<<<64, 256>>>(w_value, pwv, (size_t)DM * DM);
    f32_to_f16<<<64, 256>>>(w_out, pwo, (size_t)DM * DM);
    pack_split_woa<<<320, 256>>>(w_off, b_off, w_attn, b_attn, pwhi, pwlo, pboa);

    // 1. value = ehs @ w_value^T + b_value
    gemm_a32w16<<<MVAL / 64, 256, smem_val>>>(ehs, pwv, b_value, pval, MVAL);
    // 2. offsets+attn projection (split-fp16 TC)
    gemm_dual_tc<<<BQ / 64, 256, smem_dual>>>(hs, pwhi, pwlo, pboa, poa, BQ);
    // 3. softmax + bilinear sampling + weighted sum
    msda_sample2<<<BQ, 256>>>(pval, poa, refp, pmsda);
    // 4. out = msda @ w_out^T + b_out
    gemm_a32w16<<<BQ / 64, 256, smem_val>>>(pmsda, pwo, b_out, out, BQ);
}

// round 9
// speedup vs baseline: 1.7162x; 1.0313x over previous
#include <cuda_runtime.h>
#include <cuda_fp16.h>
#include <cstdint>
#include <math.h>

// Problem constants
#define B_   16
#define Q_   300
#define S_   8400
#define DM   256
#define NH   8
#define HD   32
#define LP_  12
#define BQ   (B_*Q_)          // 4800
#define MVAL (B_*S_)          // 134400

// Scratch (static device globals — no allocation)
__device__ __half g_value_h[(size_t)MVAL * DM];  // [B,S,256] fp16 (68.8 MB)
__device__ float  g_oa[(size_t)BQ * 288];        // offsets(192)+attn logits(96)
__device__ float  g_msda[(size_t)BQ * DM];       // sampled output fp32
__device__ __half g_wv_h[DM * DM];               // w_value fp16
__device__ __half g_wo_h[DM * DM];               // w_out fp16
__device__ __half g_woa_hi[320 * DM];            // fused off+attn W, fp16 hi
__device__ __half g_woa_lo[320 * DM];            // fused off+attn W, fp16 lo
__device__ float  g_boa[320];                    // fused bias

// ===========================================================================
// weight prep kernels (tiny, one-time per launch)
// ===========================================================================
__global__ __launch_bounds__(256) void f32_to_f16(
    const float* __restrict__ src, __half* __restrict__ dst, size_t n)
{
    size_t stride = (size_t)gridDim.x * blockDim.x * 8;
    for (size_t i = ((size_t)blockIdx.x * blockDim.x + threadIdx.x) * 8;
         i < n; i += stride) {
        float4 a = *(const float4*)(src + i);
        float4 b = *(const float4*)(src + i + 4);
        __half2 h0 = __floats2half2_rn(a.x, a.y);
        __half2 h1 = __floats2half2_rn(a.z, a.w);
        __half2 h2 = __floats2half2_rn(b.x, b.y);
        __half2 h3 = __floats2half2_rn(b.z, b.w);
        uint4 o;
        o.x = *(uint32_t*)&h0; o.y = *(uint32_t*)&h1;
        o.z = *(uint32_t*)&h2; o.w = *(uint32_t*)&h3;
        *(uint4*)(dst + i) = o;
    }
}

// Pack Woff(192)+Wattn(96)+zeros(32) rows into hi/lo fp16 split + bias.
__global__ __launch_bounds__(256) void pack_split_woa(
    const float* __restrict__ Woff,  const float* __restrict__ boff,
    const float* __restrict__ Wattn, const float* __restrict__ battn,
    __half* __restrict__ Whi, __half* __restrict__ Wlo,
    float* __restrict__ bdst)
{
    const int r = blockIdx.x;      // 0..319
    const int k = threadIdx.x;     // 0..255
    float v = 0.f;
    if (r < 192)      v = Woff[r * DM + k];
    else if (r < 288) v = Wattn[(r - 192) * DM + k];
    __half h = __float2half_rn(v);
    Whi[r * DM + k] = h;
    Wlo[r * DM + k] = __float2half_rn(v - __half2float(h));
    if (k == 0) bdst[r] = (r < 192) ? boff[r] : (r < 288 ? battn[r - 192] : 0.f);
}

// ===========================================================================
// helpers
// ===========================================================================
__device__ __forceinline__ void mma_m16n8k16_f16(
    float c[4], const uint32_t a[4], const uint32_t b[2])
{
    asm volatile(
        "mma.sync.aligned.m16n8k16.row.col.f32.f16.f16.f32 "
        "{%0,%1,%2,%3}, {%4,%5,%6,%7}, {%8,%9}, {%0,%1,%2,%3};"
        : "+f"(c[0]), "+f"(c[1]), "+f"(c[2]), "+f"(c[3])
        : "r"(a[0]), "r"(a[1]), "r"(a[2]), "r"(a[3]),
          "r"(b[0]), "r"(b[1]));
}
__device__ __forceinline__ uint32_t pack_f16x2(float lo, float hi) {
    uint32_t r;
    asm("cvt.rn.f16x2.f32 %0, %1, %2;" : "=r"(r) : "f"(hi), "f"(lo));
    return r;
}
__device__ __forceinline__ void cp_async16(uint32_t dst, const void* src, bool valid) {
    int sz = valid ? 16 : 0;
    asm volatile("cp.async.cg.shared.global [%0], [%1], 16, %2;"
                 :: "r"(dst), "l"(src), "r"(sz));
}
#define CP_COMMIT()  asm volatile("cp.async.commit_group;" ::: "memory")
#define CP_WAIT(N)   asm volatile("cp.async.wait_group %0;" :: "n"(N) : "memory")

// ===========================================================================
// Mixed GEMM: C[M,256] = f16(A_f32[M,256]) @ W_f16[256,256]^T + bias
// CTA tile 64x256, 8 warps (2m x 4n), warp tile 32x64, 2 CTAs/SM.
// BK=32, 3-stage cp.async. A kept fp32 in SMEM, cvt at fragment load.
// HALF_OUT: write C as fp16 (value GEMM) or fp32 (output projection).
// ===========================================================================
#define GK      256
#define CBK     32
#define CNCH    (GK / CBK)      // 8 chunks
#define PADA    40              // fp32 words per A row
#define PADB    20              // packed f16 words per B row
#define CAW     (64 * PADA)     // 2560 words
#define CBW     (256 * PADB)    // 5120 words
#define CSTAGEW (CAW + CBW)     // 7680 words
#define CNSTAGE 3

template <bool HALF_OUT>
__global__ __launch_bounds__(256, 2) void gemm_a32w16(
    const float* __restrict__ A, const __half* __restrict__ W,
    const float* __restrict__ bias, void* __restrict__ Cv, int M)
{
    extern __shared__ uint32_t sm[];

    const int tid  = threadIdx.x;
    const int wid  = tid >> 5;
    const int lane = tid & 31;
    const int grp  = lane >> 2;
    const int tig  = lane & 3;

    const int wm = (wid & 1) * 32;
    const int wn = (wid >> 1) * 64;
    const int m0 = blockIdx.x * 64;

    const uint32_t smem_u32 = (uint32_t)__cvta_generic_to_shared(sm);

    float acc[2][8][4];
#pragma unroll
    for (int i = 0; i < 2; i++)
#pragma unroll
        for (int j = 0; j < 8; j++)
#pragma unroll
            for (int l = 0; l < 4; l++) acc[i][j][l] = 0.f;

    auto issue = [&](int c, int s) {
        const uint32_t abase = smem_u32 + (uint32_t)(s * CSTAGEW) * 4u;
        const uint32_t bbase = abase + (uint32_t)CAW * 4u;
        const int k0 = c * CBK;
#pragma unroll
        for (int it = 0; it < 2; ++it) {
            int idx = tid + it * 256;
            int row = idx >> 3, col = idx & 7;
            bool v = (m0 + row) < M;
            const float* src = A + (size_t)(m0 + row) * GK + k0 + col * 4;
            cp_async16(abase + (uint32_t)(row * PADA + col * 4) * 4u, src, v);
        }
#pragma unroll
        for (int it = 0; it < 4; ++it) {
            int idx = tid + it * 256;
            int row = idx >> 2, col = idx & 3;
            const __half* src = W + (size_t)row * GK + k0 + col * 8;
            cp_async16(bbase + (uint32_t)(row * PADB + col * 4) * 4u, src, true);
        }
        CP_COMMIT();
    };

    issue(0, 0);
    issue(1, 1);

    for (int c = 0; c < CNCH; ++c) {
        CP_WAIT(1);
        __syncthreads();

        if (c + 2 < CNCH) issue(c + 2, (c + 2) % CNSTAGE);
        else CP_COMMIT();

        const uint32_t* sAw = sm + (c % CNSTAGE) * CSTAGEW;
        const float*    sA  = (const float*)sAw;
        const uint32_t* sB  = sAw + CAW;

#pragma unroll
        for (int kk = 0; kk < 2; ++kk) {
            const int ka = kk * 16 + 2 * tig;
            const int kb = kk * 8 + tig;
            uint32_t af[2][4];
#pragma unroll
            for (int mf = 0; mf < 2; ++mf) {
                const int m = wm + mf * 16 + grp;
                float2 a0 = *(const float2*)(sA + m * PADA + ka);
                float2 a1 = *(const float2*)(sA + (m + 8) * PADA + ka);
                float2 a2 = *(const float2*)(sA + m * PADA + ka + 8);
                float2 a3 = *(const float2*)(sA + (m + 8) * PADA + ka + 8);
                af[mf][0] = pack_f16x2(a0.x, a0.y);
                af[mf][1] = pack_f16x2(a1.x, a1.y);
                af[mf][2] = pack_f16x2(a2.x, a2.y);
                af[mf][3] = pack_f16x2(a3.x, a3.y);
            }
#pragma unroll
            for (int nf = 0; nf < 8; ++nf) {
                const int n = wn + nf * 8 + grp;
                uint32_t bf[2];
                bf[0] = sB[n * PADB + kb];
                bf[1] = sB[n * PADB + kb + 4];
#pragma unroll
                for (int mf = 0; mf < 2; ++mf)
                    mma_m16n8k16_f16(acc[mf][nf], af[mf], bf);
            }
        }
    }

    // ---- epilogue ----
#pragma unroll
    for (int mf = 0; mf < 2; ++mf) {
        const int mlo = m0 + wm + mf * 16 + grp;
#pragma unroll
        for (int nf = 0; nf < 8; ++nf) {
            const int col = wn + nf * 8 + 2 * tig;
            const float bx = __ldg(&bias[col]);
            const float by = __ldg(&bias[col + 1]);
            if (HALF_OUT) {
                __half* C = (__half*)Cv;
                if (mlo < M) {
                    uint32_t p = pack_f16x2(acc[mf][nf][0] + bx, acc[mf][nf][1] + by);
                    *(uint32_t*)(C + (size_t)mlo * DM + col) = p;
                }
                if (mlo + 8 < M) {
                    uint32_t p = pack_f16x2(acc[mf][nf][2] + bx, acc[mf][nf][3] + by);
                    *(uint32_t*)(C + (size_t)(mlo + 8) * DM + col) = p;
                }
            } else {
                float* C = (float*)Cv;
                if (mlo < M) {
                    float2 v = make_float2(acc[mf][nf][0] + bx, acc[mf][nf][1] + by);
                    *(float2*)(C + (size_t)mlo * DM + col) = v;
                }
                if (mlo + 8 < M) {
                    float2 v = make_float2(acc[mf][nf][2] + bx, acc[mf][nf][3] + by);
                    *(float2*)(C + (size_t)(mlo + 8) * DM + col) = v;
                }
            }
        }
    }
}

// ===========================================================================
// Split-fp16 TC GEMM for offsets+attn: C[4800,288] = hs @ Woa^T + b
// 3-term compensated fp16: C = Ah*Bh + Ah*Bl + Al*Bh (error ~2e-7).
// ===========================================================================
#define DAW     (64 * PADA)          // 2560 words
#define DBW     (320 * PADB)         // 6400 words
#define DSTAGEW (DAW + 2 * DBW)      // 15360 words
#define DNSTAGE 3

__global__ __launch_bounds__(256) void gemm_dual_tc(
    const float* __restrict__ A,
    const __half* __restrict__ Whi, const __half* __restrict__ Wlo,
    const float* __restrict__ bias, float* __restrict__ C, int M)
{
    extern __shared__ uint32_t sm[];

    const int tid  = threadIdx.x;
    const int wid  = tid >> 5;
    const int lane = tid & 31;
    const int grp  = lane >> 2;
    const int tig  = lane & 3;

    const int wm = (wid & 1) * 32;
    const int wn = (wid >> 1) * 80;
    const int m0 = blockIdx.x * 64;

    const uint32_t smem_u32 = (uint32_t)__cvta_generic_to_shared(sm);

    float acc[2][10][4];
#pragma unroll
    for (int i = 0; i < 2; i++)
#pragma unroll
        for (int j = 0; j < 10; j++)
#pragma unroll
            for (int l = 0; l < 4; l++) acc[i][j][l] = 0.f;

    auto issue = [&](int c, int s) {
        const uint32_t abase  = smem_u32 + (uint32_t)(s * DSTAGEW) * 4u;
        const uint32_t bhbase = abase + (uint32_t)DAW * 4u;
        const uint32_t blbase = bhbase + (uint32_t)DBW * 4u;
        const int k0 = c * CBK;
#pragma unroll
        for (int it = 0; it < 2; ++it) {
            int idx = tid + it * 256;
            int row = idx >> 3, col = idx & 7;
            bool v = (m0 + row) < M;
            const float* src = A + (size_t)(m0 + row) * GK + k0 + col * 4;
            cp_async16(abase + (uint32_t)(row * PADA + col * 4) * 4u, src, v);
        }
#pragma unroll
        for (int it = 0; it < 5; ++it) {
            int idx = tid + it * 256;
            int row = idx >> 2, col = idx & 3;
            const __half* srch = Whi + (size_t)row * GK + k0 + col * 8;
            cp_async16(bhbase + (uint32_t)(row * PADB + col * 4) * 4u, srch, true);
        }
#pragma unroll
        for (int it = 0; it < 5; ++it) {
            int idx = tid + it * 256;
            int row = idx >> 2, col = idx & 3;
            const __half* srcl = Wlo + (size_t)row * GK + k0 + col * 8;
            cp_async16(blbase + (uint32_t)(row * PADB + col * 4) * 4u, srcl, true);
        }
        CP_COMMIT();
    };

    issue(0, 0);
    issue(1, 1);

    for (int c = 0; c < CNCH; ++c) {
        CP_WAIT(1);
        __syncthreads();

        if (c + 2 < CNCH) issue(c + 2, (c + 2) % DNSTAGE);
        else CP_COMMIT();

        const uint32_t* sAw = sm + (c % DNSTAGE) * DSTAGEW;
        const float*    sA  = (const float*)sAw;
        const uint32_t* sBh = sAw + DAW;
        const uint32_t* sBl = sBh + DBW;

#pragma unroll
        for (int kk = 0; kk < 2; ++kk) {
            const int ka = kk * 16 + 2 * tig;
            const int kb = kk * 8 + tig;
            uint32_t ah[2][4], al[2][4];
#pragma unroll
            for (int mf = 0; mf < 2; ++mf) {
                const int m = wm + mf * 16 + grp;
                float2 a0 = *(const float2*)(sA + m * PADA + ka);
                float2 a1 = *(const float2*)(sA + (m + 8) * PADA + ka);
                float2 a2 = *(const float2*)(sA + m * PADA + ka + 8);
                float2 a3 = *(const float2*)(sA + (m + 8) * PADA + ka + 8);
#pragma unroll
                for (int q = 0; q < 4; ++q) {
                    float2 av = (q == 0) ? a0 : (q == 1) ? a1 : (q == 2) ? a2 : a3;
                    uint32_t hi = pack_f16x2(av.x, av.y);
                    float2 hf = __half22float2(*(__half2*)&hi);
                    ah[mf][q] = hi;
                    al[mf][q] = pack_f16x2(av.x - hf.x, av.y - hf.y);
                }
            }
#pragma unroll
            for (int nf = 0; nf < 10; ++nf) {
                const int n = wn + nf * 8 + grp;
                uint32_t bh[2], bl[2];
                bh[0] = sBh[n * PADB + kb];
                bh[1] = sBh[n * PADB + kb + 4];
                bl[0] = sBl[n * PADB + kb];
                bl[1] = sBl[n * PADB + kb + 4];
#pragma unroll
                for (int mf = 0; mf < 2; ++mf) {
                    mma_m16n8k16_f16(acc[mf][nf], ah[mf], bh);
                    mma_m16n8k16_f16(acc[mf][nf], ah[mf], bl);
                    mma_m16n8k16_f16(acc[mf][nf], al[mf], bh);
                }
            }
        }
    }

#pragma unroll
    for (int mf = 0; mf < 2; ++mf) {
        const int mlo = m0 + wm + mf * 16 + grp;
#pragma unroll
        for (int nf = 0; nf < 10; ++nf) {
            const int col = wn + nf * 8 + 2 * tig;
            if (col >= 288) continue;
            const float bx = __ldg(&bias[col]);
            const float by = __ldg(&bias[col + 1]);
            if (mlo < M) {
                float2 v = make_float2(acc[mf][nf][0] + bx, acc[mf][nf][1] + by);
                *(float2*)(C + (size_t)mlo * 288 + col) = v;
            }
            if (mlo + 8 < M) {
                float2 v = make_float2(acc[mf][nf][2] + bx, acc[mf][nf][3] + by);
                *(float2*)(C + (size_t)(mlo + 8) * 288 + col) = v;
            }
        }
    }
}

// ---------------------------------------------------------------------------
// Sampling kernel: block per (b,q). value is fp16 (L2-resident at 68.8 MB).
// ---------------------------------------------------------------------------
__global__ __launch_bounds__(256) void msda_sample2(
    const __half* __restrict__ value,
    const float* __restrict__ oa,
    const float* __restrict__ refp,
    float* __restrict__ out)
{
    __shared__ float  s_logit[96];
    __shared__ float2 s_mxinv[8];
    __shared__ int4   s_ofs[96];
    __shared__ float4 s_wts[96];

    const int bq = blockIdx.x;
    const int b  = bq / Q_;
    const int t  = threadIdx.x;

    if (t < 96) s_logit[t] = oa[(size_t)bq * 288 + 192 + t];
    __syncthreads();

    if (t < 8) {
        float mx = -1e30f;
#pragma unroll
        for (int p = 0; p < LP_; p++) mx = fmaxf(mx, s_logit[t * LP_ + p]);
        float s = 0.f;
#pragma unroll
        for (int p = 0; p < LP_; p++) s += __expf(s_logit[t * LP_ + p] - mx);
        s_mxinv[t] = make_float2(mx, 1.f / s);
    }
    __syncthreads();

    if (t < 96) {
        const int h = t / LP_;
        const int p = t - h * LP_;
        const float2 mi = s_mxinv[h];
        const float aw = __expf(s_logit[t] - mi.x) * mi.y;

        const float rx = refp[bq * 4 + 0];
        const float ry = refp[bq * 4 + 1];
        const float rw = refp[bq * 4 + 2];
        const float rh = refp[bq * 4 + 3];

        const float ox = oa[(size_t)bq * 288 + h * 24 + 2 * p + 0];
        const float oy = oa[(size_t)bq * 288 + h * 24 + 2 * p + 1];

        const int lvl   = p >> 2;
        const int Wl    = (lvl == 0) ? 80 : (lvl == 1) ? 40 : 20;
        const int start = (lvl == 0) ? 0 : (lvl == 1) ? 6400 : 8000;

        const float gx = (rx + ox * 0.125f * rw) * (float)Wl - 0.5f;
        const float gy = (ry + oy * 0.125f * rh) * (float)Wl - 0.5f;

        const float x0f = floorf(gx), y0f = floorf(gy);
        const int x0 = (int)x0f, y0 = (int)y0f;
        const int x1 = x0 + 1,  y1 = y0 + 1;
        const float wx1 = gx - x0f, wx0 = 1.f - wx1;
        const float wy1 = gy - y0f, wy0 = 1.f - wy1;

        const bool xv0 = (x0 >= 0) & (x0 < Wl);
        const bool xv1 = (x1 >= 0) & (x1 < Wl);
        const bool yv0 = (y0 >= 0) & (y0 < Wl);
        const bool yv1 = (y1 >= 0) & (y1 < Wl);

        const int x0c = min(max(x0, 0), Wl - 1);
        const int x1c = min(max(x1, 0), Wl - 1);
        const int y0c = min(max(y0, 0), Wl - 1);
        const int y1c = min(max(y1, 0), Wl - 1);

        const int rb = b * S_ + start;
        const int r0 = rb + y0c * Wl;
        const int r1 = rb + y1c * Wl;
        const int hb = h * HD;

        int4 o;
        o.x = (r0 + x0c) * DM + hb;
        o.y = (r0 + x1c) * DM + hb;
        o.z = (r1 + x0c) * DM + hb;
        o.w = (r1 + x1c) * DM + hb;

        float4 w;
        w.x = aw * wx0 * wy0 * (float)(xv0 & yv0);
        w.y = aw * wx1 * wy0 * (float)(xv1 & yv0);
        w.z = aw * wx0 * wy1 * (float)(xv0 & yv1);
        w.w = aw * wx1 * wy1 * (float)(xv1 & yv1);

        s_ofs[t] = o;
        s_wts[t] = w;
    }
    __syncthreads();

    const int h    = t >> 5;
    const int lane = t & 31;
    float acc = 0.f;
#pragma unroll
    for (int p = 0; p < LP_; p++) {
        const int4   o = s_ofs[h * LP_ + p];
        const float4 w = s_wts[h * LP_ + p];
        acc += w.x * __half2float(__ldg(&value[o.x + lane]));
        acc += w.y * __half2float(__ldg(&value[o.y + lane]));
        acc += w.z * __half2float(__ldg(&value[o.z + lane]));
        acc += w.w * __half2float(__ldg(&value[o.w + lane]));
    }
    out[(size_t)bq * DM + h * HD + lane] = acc;
}

// ---------------------------------------------------------------------------
extern "C" void kernel_launch(void* const* d_in, const int* in_sizes, int n_in,
                              void* d_out, int out_size)
{
    const float* hs      = (const float*)d_in[0];
    const float* ehs     = (const float*)d_in[1];
    const float* refp    = (const float*)d_in[2];
    const float* w_value = (const float*)d_in[3];
    const float* b_value = (const float*)d_in[4];
    const float* w_off   = (const float*)d_in[5];
    const float* b_off   = (const float*)d_in[6];
    const float* w_attn  = (const float*)d_in[7];
    const float* b_attn  = (const float*)d_in[8];
    const float* w_out   = (const float*)d_in[9];
    const float* b_out   = (const float*)d_in[10];
    float* out = (float*)d_out;

    float  *poa, *pmsda, *pboa;
    __half *pvalh, *pwv, *pwo, *pwhi, *pwlo;
    cudaGetSymbolAddress((void**)&pvalh, g_value_h);
    cudaGetSymbolAddress((void**)&poa,   g_oa);
    cudaGetSymbolAddress((void**)&pmsda, g_msda);
    cudaGetSymbolAddress((void**)&pwv,   g_wv_h);
    cudaGetSymbolAddress((void**)&pwo,   g_wo_h);
    cudaGetSymbolAddress((void**)&pwhi,  g_woa_hi);
    cudaGetSymbolAddress((void**)&pwlo,  g_woa_lo);
    cudaGetSymbolAddress((void**)&pboa,  g_boa);

    const int smem_val  = CNSTAGE * CSTAGEW * 4;   // 92160 B
    const int smem_dual = DNSTAGE * DSTAGEW * 4;   // 184320 B
    cudaFuncSetAttribute(gemm_a32w16<true>,
                         cudaFuncAttributeMaxDynamicSharedMemorySize, smem_val);
    cudaFuncSetAttribute(gemm_a32w16<false>,
                         cudaFuncAttributeMaxDynamicSharedMemorySize, smem_val);
    cudaFuncSetAttribute(gemm_dual_tc,
                         cudaFuncAttributeMaxDynamicSharedMemorySize, smem_dual);

    // 0. weight prep (tiny)
    f32_to_f16<<<64, 256>>>(w_value, pwv, (size_t)DM * DM);
    f32_to_f16<<<64, 256>>>(w_out, pwo, (size_t)DM * DM);
    pack_split_woa<<<320, 256>>>(w_off, b_off, w_attn, b_attn, pwhi, pwlo, pboa);

    // 1. value = ehs @ w_value^T + b_value  (fp16 output)
    gemm_a32w16<true><<<MVAL / 64, 256, smem_val>>>(ehs, pwv, b_value,
                                                    (void*)pvalh, MVAL);
    // 2. offsets+attn projection (split-fp16 TC)
    gemm_dual_tc<<<BQ / 64, 256, smem_dual>>>(hs, pwhi, pwlo, pboa, poa, BQ);
    // 3. softmax + bilinear sampling + weighted sum (fp16 value reads)
    msda_sample2<<<BQ, 256>>>(pvalh, poa, refp, pmsda);
    // 4. out = msda @ w_out^T + b_out  (fp32 output)
    gemm_a32w16<false><<<BQ / 64, 256, smem_val>>>(pmsda, pwo, b_out,
                                                   (void*)out, BQ);
}